// round 14
// baseline (speedup 1.0000x reference)
#include <cuda_runtime.h>
#include <cuda_fp16.h>
#include <cuda_bf16.h>
#include <math.h>

// DECO decomposed (len-1 softmax == 1 → Wq/Wk/W_scene dead):
//   att  = (feat @ W_contact + b_c) @ Wv @ Wo            [16,1024]
//   cont = sigmoid(att @ W_cls + b_cls)                  [16,6890]
//   a    = att @ W_ft1[:1024] + b_ft1                    [16,512]
//   P    = pos_emb @ W_ft1[1024:]   (HMMA fp16 2-term, stored fp16)
//   sem[b,c,v] = mask * (relu(a[b]+P[v]) @ W_ft2 + b2)[c]
// R14: TWO launches. k_front = prep + zero + chain (5 staged GEMMs w/ grid
// barriers) with P tiles overlapped onto idle CTAs + final P phase.
// k_sem = persistent fp16 1-term main GEMM (R13, unchanged).

#define BB   16
#define DF   1536
#define DD   1024
#define VV   6890
#define PDIM 256
#define HID  512
#define CC   133
#define NC   144
#define BROWS 136
#define NPERS 148
#define NPTILE 432          // 54 vb x 8 hb

typedef unsigned long long u64;
typedef unsigned int u32;

__device__ float g_part[4 * BB * DD];
__device__ float g_tmp [4 * BB * DD];
__device__ float g_att [4 * BB * DD];
__device__ float g_a   [4 * BB * HID];
__device__ __align__(16) __half g_Ph[VV * HID];
__device__ int   g_idx [BB * VV];
__device__ int   g_cnt [BB];
__device__ __align__(16) __half g_Bimg[8 * BROWS * 64];
__device__ __align__(16) __half g_B1h[4 * 512 * 64];   // W_ft1p fp16, swizzled
__device__ int   g_bar_arrive;
__device__ unsigned int g_bar_gen;

__device__ __forceinline__ u64 pk2(float lo, float hi) {
    u64 r; asm("mov.b64 %0, {%1, %2};" : "=l"(r) : "f"(lo), "f"(hi)); return r;
}
__device__ __forceinline__ void upk2(u64 v, float& lo, float& hi) {
    asm("mov.b64 {%0, %1}, %2;" : "=f"(lo), "=f"(hi) : "l"(v));
}
__device__ __forceinline__ u64 ffma2(u64 a, u64 b, u64 c) {
    u64 d; asm("fma.rn.f32x2 %0, %1, %2, %3;" : "=l"(d) : "l"(a), "l"(b), "l"(c));
    return d;
}
__device__ __forceinline__ u32 smem_u32(const void* p) {
    u32 a; asm("{ .reg .u64 t; cvta.to.shared.u64 t, %1; cvt.u32.u64 %0, t; }"
               : "=r"(a) : "l"(p));
    return a;
}
__device__ __forceinline__ void ldm_x4(u32* r, u32 addr) {
    asm volatile("ldmatrix.sync.aligned.m8n8.x4.shared.b16 {%0,%1,%2,%3}, [%4];"
        : "=r"(r[0]), "=r"(r[1]), "=r"(r[2]), "=r"(r[3]) : "r"(addr));
}
__device__ __forceinline__ void ldm_x2(u32* r, u32 addr) {
    asm volatile("ldmatrix.sync.aligned.m8n8.x2.shared.b16 {%0,%1}, [%2];"
        : "=r"(r[0]), "=r"(r[1]) : "r"(addr));
}
__device__ __forceinline__ void mma_f16(float* d, const u32* a, const u32* b) {
    asm volatile("mma.sync.aligned.m16n8k16.row.col.f32.f16.f16.f32 "
        "{%0,%1,%2,%3}, {%4,%5,%6,%7}, {%8,%9}, {%0,%1,%2,%3};"
        : "+f"(d[0]), "+f"(d[1]), "+f"(d[2]), "+f"(d[3])
        : "r"(a[0]), "r"(a[1]), "r"(a[2]), "r"(a[3]), "r"(b[0]), "r"(b[1]));
}
__device__ __forceinline__ u32 h2u(__half2 h) {
    u32 r; asm("mov.b32 %0, %1;" : "=r"(r) : "r"(*(u32*)&h)); return r;
}
__device__ __forceinline__ void cpasync16(u32 dst, const void* src) {
    asm volatile("cp.async.cg.shared.global [%0], [%1], 16;"
                 :: "r"(dst), "l"(src) : "memory");
}
__device__ __forceinline__ void cpasync_commit() {
    asm volatile("cp.async.commit_group;" ::: "memory");
}
__device__ __forceinline__ void cpasync_wait0() {
    asm volatile("cp.async.wait_group 0;" ::: "memory");
}

__device__ __forceinline__ void grid_bar() {
    __syncthreads();
    if (threadIdx.x == 0) {
        __threadfence();
        unsigned gen = atomicAdd(&g_bar_gen, 0u);
        int a = atomicAdd(&g_bar_arrive, 1);
        if (a == NPERS - 1) {
            g_bar_arrive = 0;
            __threadfence();
            atomicAdd(&g_bar_gen, 1u);
        } else {
            while (atomicAdd(&g_bar_gen, 0u) == gen) {}
        }
        __threadfence();
    }
    __syncthreads();
}

// k_sem smem layout (bytes)
#define SM_AS     0
#define SM_H(bf)  (2048 + (bf) * 18432)
#define SM_BALL   38912
#define SM_BC(ch) (SM_BALL + (ch) * 17408)
#define SM_TOT    178176
// k_front smem: chain view (in_s 9216 + red 65536 = 74752) OR
// P-tile view (HH 16384 | HL 16384 | B 8192 = 40960). Padded for 1 CTA/SM.
#define SMF_TOT   122880
#define SMP_HH 0
#define SMP_HL 16384
#define SMP_B  32768

// ---------------------------------------------------------------------------
// Device fn: split-K skinny GEMM vblock (512 thr = 32 cols x 16 K-slices).
// ---------------------------------------------------------------------------
__device__ void skinny_dev(const float* __restrict__ in,
                           const float* __restrict__ W,
                           const float* __restrict__ bias,
                           float* __restrict__ out,
                           int K, int N, int nsum, int colb, int ky,
                           float* in_s, float* red)
{
    const int tid  = threadIdx.x;
    const int col  = tid & 31;
    const int slc  = tid >> 5;
    const int colg = colb * 32 + col;
    const int colc = colg < N ? colg : N - 1;
    const int kspan = K >> 2;
    const int kbase = ky * kspan;

    u64 acc2[8];
#pragma unroll
    for (int m = 0; m < 8; m++) acc2[m] = 0ull;

    for (int k0 = kbase; k0 < kbase + kspan; k0 += 128) {
        __syncthreads();
#pragma unroll
        for (int i = 0; i < 4; i++) {
            int e = tid + 512 * i;
            int b = e >> 7, k = e & 127;
            float s = 0.f;
            for (int sc = 0; sc < nsum; sc++)
                s += in[(size_t)sc * BB * K + b * K + k0 + k];
            in_s[k * 18 + b] = s;
        }
        __syncthreads();
#pragma unroll
        for (int kk = 0; kk < 8; kk++) {
            int k = slc * 8 + kk;
            float w = W[(size_t)(k0 + k) * N + colc];
            u64 w2 = pk2(w, w);
            const u64* ip = (const u64*)&in_s[k * 18];
#pragma unroll
            for (int m = 0; m < 8; m++)
                acc2[m] = ffma2(ip[m], w2, acc2[m]);
        }
    }
    float* rp = &red[slc * 512 + col * 16];
#pragma unroll
    for (int m = 0; m < 8; m++) {
        float lo, hi; upk2(acc2[m], lo, hi);
        rp[2 * m] = lo; rp[2 * m + 1] = hi;
    }
    __syncthreads();
    {
        int c = tid >> 4, b = tid & 15;
        float s = 0.f;
#pragma unroll
        for (int sl = 0; sl < 16; sl++) s += red[sl * 512 + c * 16 + b];
        int cg = colb * 32 + c;
        if (cg < N) {
            float bb = (bias && ky == 0) ? bias[cg] : 0.f;
            out[(size_t)ky * BB * N + b * N + cg] = s + bb;
        }
    }
    __syncthreads();
}

// ---------------------------------------------------------------------------
// Device fn: cont vblock (64 cols).
// ---------------------------------------------------------------------------
__device__ void cont_dev(const float* __restrict__ att,
                         const float* __restrict__ Wc,
                         const float* __restrict__ bc,
                         float* __restrict__ out, int vb,
                         float* in_s, float* red)
{
    const int tid = threadIdx.x;
    const int cp  = tid & 31;
    const int slc = tid >> 5;
    const int col0 = vb * 64 + 2 * cp;
    const int colc = col0 <= VV - 2 ? col0 : VV - 2;

    u64 acc[2][8];
#pragma unroll
    for (int j = 0; j < 2; j++)
#pragma unroll
        for (int m = 0; m < 8; m++) acc[j][m] = 0ull;

    for (int k0 = 0; k0 < DD; k0 += 128) {
        __syncthreads();
#pragma unroll
        for (int i = 0; i < 4; i++) {
            int e = tid + 512 * i;
            int b = e >> 7, k = e & 127;
            float s = 0.f;
#pragma unroll
            for (int sc = 0; sc < 4; sc++)
                s += att[(size_t)sc * BB * DD + b * DD + k0 + k];
            in_s[k * 18 + b] = s;
        }
        __syncthreads();
#pragma unroll
        for (int kk = 0; kk < 8; kk++) {
            int k = slc * 8 + kk;
            float2 w = *(const float2*)&Wc[(size_t)(k0 + k) * VV + colc];
            u64 w0 = pk2(w.x, w.x), w1 = pk2(w.y, w.y);
            const u64* ip = (const u64*)&in_s[k * 18];
#pragma unroll
            for (int m = 0; m < 8; m++) {
                acc[0][m] = ffma2(ip[m], w0, acc[0][m]);
                acc[1][m] = ffma2(ip[m], w1, acc[1][m]);
            }
        }
    }
#pragma unroll
    for (int j = 0; j < 2; j++) {
        float* rp = &red[slc * 1024 + (2 * cp + j) * 16];
#pragma unroll
        for (int m = 0; m < 8; m++) {
            float lo, hi; upk2(acc[j][m], lo, hi);
            rp[2 * m] = lo; rp[2 * m + 1] = hi;
        }
    }
    __syncthreads();
    for (int o = tid; o < 1024; o += 512) {
        int c = o >> 4, b = o & 15;
        float s = 0.f;
#pragma unroll
        for (int sl = 0; sl < 16; sl++) s += red[sl * 1024 + c * 16 + b];
        int cg = vb * 64 + c;
        if (cg < VV)
            out[b * VV + cg] = 1.f / (1.f + expf(-(s + bc[cg])));
    }
    __syncthreads();
}

// ---------------------------------------------------------------------------
// Device fn: order-preserving compaction for batch b.
// ---------------------------------------------------------------------------
__device__ void compact_dev(const float* __restrict__ cont,
                            int* __restrict__ idx, int* __restrict__ cnt,
                            int b)
{
    const int tid = threadIdx.x;
    const int lane = tid & 31, wrp = tid >> 5;
    __shared__ int wexc[16];
    __shared__ int s_base, s_tot;
    if (tid == 0) s_base = 0;
    __syncthreads();
    for (int v0 = 0; v0 < VV; v0 += 512) {
        int v = v0 + tid;
        int m = (v < VV) && (cont[b * VV + v] > 0.5f);
        unsigned bal = __ballot_sync(0xffffffffu, m);
        int wsum = __popc(bal);
        int pw = __popc(bal & ((1u << lane) - 1u));
        if (lane == 0) wexc[wrp] = wsum;
        __syncthreads();
        if (tid < 16) {
            int sv = wexc[tid];
            int e = sv;
#pragma unroll
            for (int d = 1; d < 16; d <<= 1) {
                int t = __shfl_up_sync(0xffffu, e, d);
                if (tid >= d) e += t;
            }
            wexc[tid] = e - sv;
            if (tid == 15) s_tot = e;
        }
        __syncthreads();
        int pos = s_base + wexc[wrp] + pw;
        if (v < VV && m) idx[b * VV + pos] = v;
        __syncthreads();
        if (tid == 0) s_base += s_tot;
        __syncthreads();
    }
    if (tid == 0) cnt[b] = s_base;
}

// ---------------------------------------------------------------------------
// Device fn: one P tile (128 v x 64 h), K=256, fp16 2-term (pos hi+lo x W).
// 512 thr = 16 warps (8m x 2n). Writes Ph fp16.
// ---------------------------------------------------------------------------
__device__ void ptile_dev(const float* __restrict__ pos,
                          const __half* __restrict__ B1h,
                          __half* __restrict__ Ph,
                          int tile, char* smem, u32 sb)
{
    const int vb = tile >> 3, hb = tile & 7;
    const int vbase = vb * 128, hbase = hb * 64;
    const int tid = threadIdx.x;
    const int wid = tid >> 5, l = tid & 31;
    const int wm = wid & 7, wn = wid >> 3;
    const int r = tid & 127, quarter = tid >> 7;
    const int v = vbase + r;
    const int vc = v < VV ? v : VV - 1;
    const float* __restrict__ prow = pos + (size_t)vc * PDIM + quarter * 16;

    float acc[4][4];
#pragma unroll
    for (int j = 0; j < 4; j++)
#pragma unroll
        for (int q = 0; q < 4; q++) acc[j][q] = 0.f;

    for (int ch = 0; ch < 4; ch++) {
        __syncthreads();   // protect smem from previous chunk / caller state
        // producer: 16 pos values -> fp16 hi + lo, swizzled STS
        {
            float x[16];
#pragma unroll
            for (int q = 0; q < 4; q++) {
                float4 p4 = *(const float4*)(prow + ch * 64 + 4 * q);
                x[4*q+0] = p4.x; x[4*q+1] = p4.y; x[4*q+2] = p4.z; x[4*q+3] = p4.w;
            }
            u32 hw[8], lw[8];
#pragma unroll
            for (int i = 0; i < 8; i++) {
                __half h0 = __float2half_rn(x[2*i]);
                __half h1 = __float2half_rn(x[2*i+1]);
                __half l0 = __float2half_rn(x[2*i]   - __half2float(h0));
                __half l1 = __float2half_rn(x[2*i+1] - __half2float(h1));
                hw[i] = (u32)__half_as_ushort(h0) | ((u32)__half_as_ushort(h1) << 16);
                lw[i] = (u32)__half_as_ushort(l0) | ((u32)__half_as_ushort(l1) << 16);
            }
            const u32 c0 = (u32)(quarter * 2);
            const u32 q7 = (u32)r & 7u;
            const u32 off0 = (u32)(r << 7) + ((c0 ^ q7) << 4);
            const u32 off1 = (u32)(r << 7) + (((c0 + 1u) ^ q7) << 4);
            asm volatile("st.shared.v4.b32 [%0], {%1,%2,%3,%4};"
                :: "r"(sb + SMP_HH + off0), "r"(hw[0]), "r"(hw[1]), "r"(hw[2]), "r"(hw[3]) : "memory");
            asm volatile("st.shared.v4.b32 [%0], {%1,%2,%3,%4};"
                :: "r"(sb + SMP_HH + off1), "r"(hw[4]), "r"(hw[5]), "r"(hw[6]), "r"(hw[7]) : "memory");
            asm volatile("st.shared.v4.b32 [%0], {%1,%2,%3,%4};"
                :: "r"(sb + SMP_HL + off0), "r"(lw[0]), "r"(lw[1]), "r"(lw[2]), "r"(lw[3]) : "memory");
            asm volatile("st.shared.v4.b32 [%0], {%1,%2,%3,%4};"
                :: "r"(sb + SMP_HL + off1), "r"(lw[4]), "r"(lw[5]), "r"(lw[6]), "r"(lw[7]) : "memory");
        }
        // B slice: 64 rows x 128 B = 512 uint4 (pre-swizzled)
        ((uint4*)(smem + SMP_B))[tid] =
            ((const uint4*)(B1h + (size_t)ch * 32768 + (size_t)hbase * 64))[tid];
        __syncthreads();
#pragma unroll
        for (int ks = 0; ks < 4; ks++) {
            u32 ah[4], al[4];
            {
                int ra = wm * 16 + (l & 15);
                u32 chk = (((u32)(l >> 4) + 2u * ks) ^ ((u32)ra & 7u)) << 4;
                ldm_x4(ah, sb + SMP_HH + (u32)(ra << 7) + chk);
                ldm_x4(al, sb + SMP_HL + (u32)(ra << 7) + chk);
            }
#pragma unroll
            for (int p = 0; p < 2; p++) {
                int rb = wn * 32 + p * 16 + (l & 7) + ((l >> 4) & 1) * 8;
                u32 cf = 2u * ks + ((u32)(l >> 3) & 1u);
                u32 bb[4];
                ldm_x4(bb, sb + SMP_B + (u32)(rb << 7) + ((cf ^ ((u32)rb & 7u)) << 4));
#pragma unroll
                for (int t = 0; t < 2; t++) {
                    float* d = acc[p * 2 + t];
                    mma_f16(d, ah, &bb[2 * t]);
                    mma_f16(d, al, &bb[2 * t]);
                }
            }
        }
    }
    __syncthreads();

    const int g = l >> 2, tg = l & 3;
    const int i0 = vbase + wm * 16 + g;
    const int i1 = i0 + 8;
#pragma unroll
    for (int nt = 0; nt < 4; nt++) {
        const int col = hbase + wn * 32 + nt * 8 + tg * 2;
        if (i0 < VV)
            *(__half2*)&Ph[(size_t)i0 * HID + col]
                = __floats2half2_rn(acc[nt][0], acc[nt][1]);
        if (i1 < VV)
            *(__half2*)&Ph[(size_t)i1 * HID + col]
                = __floats2half2_rn(acc[nt][2], acc[nt][3]);
    }
}

__device__ __forceinline__ void ptile1(const float* pos, const __half* B1h,
                                       __half* Ph, int t, char* smem, u32 sb)
{
    if (t >= 0 && t < NPTILE) ptile_dev(pos, B1h, Ph, t, smem, sb);
}

// ---------------------------------------------------------------------------
// MEGA front-end: phase0 prep+zero | s1..s5 chain stages with P tiles on
// idle CTAs | final P phase. grid=148, 512 thr, 6 grid barriers.
// ---------------------------------------------------------------------------
__global__ void __launch_bounds__(512, 1)
k_front(const float* __restrict__ features,
        const float* __restrict__ W_contact, const float* __restrict__ b_contact,
        const float* __restrict__ Wv, const float* __restrict__ Wo,
        const float* __restrict__ W_cls, const float* __restrict__ b_cls,
        const float* __restrict__ W_ft1, const float* __restrict__ b_ft1,
        const float* __restrict__ W_ft2, const float* __restrict__ pos,
        float* __restrict__ part, float* __restrict__ tmp,
        float* __restrict__ att, float* __restrict__ a,
        float* __restrict__ cont, int* __restrict__ idx, int* __restrict__ cnt,
        __half* __restrict__ Bimg, __half* __restrict__ B1h,
        __half* __restrict__ Ph, float4* __restrict__ zp, int n4)
{
    extern __shared__ char smemc[];
    float* in_s = (float*)smemc;
    float* red  = (float*)(smemc + 128 * 18 * 4);
    const u32 sb = smem_u32(smemc);
    const int bid = blockIdx.x;
    const int tid = threadIdx.x;

    // phase 0: prep W_ft2 images (8), prep W_ft1p fp16 image (4), zero sem
    if (bid < 8) {
        const int img = bid;
        for (int e = tid; e < BROWS * 64; e += 512) {
            int n = e >> 6, k = e & 63;
            float w = (n < CC) ? W_ft2[(size_t)(img * 64 + k) * CC + n] : 0.f;
            int off = (n << 6) + (((k >> 3) ^ (n & 7)) << 3) + (k & 7);
            Bimg[(size_t)img * (BROWS * 64) + off] = __float2half_rn(w);
        }
    } else if (bid < 12) {
        const int ch = bid - 8;
        for (int e = tid; e < 512 * 64; e += 512) {
            int n = e >> 6, k = e & 63;
            float w = W_ft1[(size_t)(DD + ch * 64 + k) * HID + n];
            int off = (n << 6) + (((k >> 3) ^ (n & 7)) << 3) + (k & 7);
            B1h[(size_t)ch * (512 * 64) + off] = __float2half_rn(w);
        }
    } else {
        for (int i = (bid - 12) * 512 + tid; i < n4; i += 136 * 512)
            zp[i] = make_float4(0.f, 0.f, 0.f, 0.f);
    }
    grid_bar();

    // s1
    if (bid < 128)
        skinny_dev(features, W_contact, b_contact, part, DF, DD, 1,
                   bid & 31, bid >> 5, in_s, red);
    else
        ptile1(pos, B1h, Ph, bid - 128, smemc, sb);
    grid_bar();
    // s2
    if (bid < 128)
        skinny_dev(part, Wv, nullptr, tmp, DD, DD, 4, bid & 31, bid >> 5, in_s, red);
    else
        ptile1(pos, B1h, Ph, 20 + bid - 128, smemc, sb);
    grid_bar();
    // s3
    if (bid < 128)
        skinny_dev(tmp, Wo, nullptr, att, DD, DD, 4, bid & 31, bid >> 5, in_s, red);
    else
        ptile1(pos, B1h, Ph, 40 + bid - 128, smemc, sb);
    grid_bar();
    // s4
    if (bid < 108)
        cont_dev(att, W_cls, b_cls, cont, bid, in_s, red);
    else
        ptile1(pos, B1h, Ph, 60 + bid - 108, smemc, sb);
    grid_bar();
    // s5
    if (bid < 64)
        skinny_dev(att, W_ft1, b_ft1, a, DD, HID, 4, bid & 15, bid >> 4, in_s, red);
    else if (bid < 80)
        compact_dev(cont, idx, cnt, bid - 64);
    else
        ptile1(pos, B1h, Ph, 100 + bid - 80, smemc, sb);
    grid_bar();
    // final P phase: remaining tiles 168..431
    ptile1(pos, B1h, Ph, 168 + bid, smemc, sb);
    ptile1(pos, B1h, Ph, 316 + bid, smemc, sb);
}

// ---------------------------------------------------------------------------
// PERSISTENT main GEMM (R13, unchanged): fp16 1-term, 512 thr (8m x 2n),
// P fp16, all B chunks smem-resident, fused scattered epilogue.
// ---------------------------------------------------------------------------
__global__ void __launch_bounds__(512, 1)
k_sem_mma(const float* __restrict__ A4,
          const __half* __restrict__ Ph,
          const __half* __restrict__ Bimg,
          const float* __restrict__ b2,
          const int* __restrict__ idx,
          const int* __restrict__ cnt,
          float* __restrict__ sem)
{
    extern __shared__ char smem[];
    const u32 sb = smem_u32(smem);
    const int tid = threadIdx.x;
    const int wid = tid >> 5;
    const int l   = tid & 31;
    const int wm = wid & 7;
    const int wn = wid >> 3;
    const int r = tid & 127;
    const int quarter = tid >> 7;
    const u32 qr = ((u32)r >> 3) & 3;
    const u32 hbase_off = (u32)(r * 144);

    {
        const char* srcB = (const char*)(Bimg);
        u32 dstB = sb + SM_BALL;
        for (int e = tid; e < 8 * 1088; e += 512)
            cpasync16(dstB + e * 16, srcB + e * 16);
        cpasync_commit();
    }

    int offv[17];
    offv[0] = 0;
#pragma unroll
    for (int b = 0; b < 16; b++)
        offv[b + 1] = offv[b] + ((cnt[b] + 127) >> 7);
    const int total = offv[16];

    float* a_sm = (float*)(smem + SM_AS);
    cpasync_wait0();

    for (int w = blockIdx.x; w < total; w += NPERS) {
        int b = 0;
#pragma unroll
        for (int t = 0; t < 15; t++) if (w >= offv[b + 1]) b++;
        const int cntb = cnt[b];
        const int ibase = (w - offv[b]) << 7;

        {
            float s = 0.f;
#pragma unroll
            for (int sc = 0; sc < 4; sc++)
                s += A4[(size_t)sc * BB * HID + b * HID + tid];
            a_sm[tid] = s;
        }

        const int ig = ibase + r;
        const int vrow = idx[b * VV + (ig < cntb ? ig : cntb - 1)];
        const __half* __restrict__ prow = Ph + (size_t)vrow * HID + quarter * 16;

        float acc[9][4];
#pragma unroll
        for (int j = 0; j < 9; j++)
#pragma unroll
            for (int q = 0; q < 4; q++) acc[j][q] = 0.f;

        uint4 pf[2];
        pf[0] = *(const uint4*)(prow);
        pf[1] = *(const uint4*)(prow + 8);
        __syncthreads();

        {
            const float* ap = a_sm + quarter * 16;
            const __half2* ph = (const __half2*)pf;
            u32 hw[8];
#pragma unroll
            for (int i = 0; i < 8; i++) {
                float2 p2 = __half22float2(ph[i]);
                float x0 = fmaxf(p2.x + ap[2*i],     0.f);
                float x1 = fmaxf(p2.y + ap[2*i + 1], 0.f);
                hw[i] = h2u(__floats2half2_rn(x0, x1));
            }
            const u32 c0 = (u32)(quarter * 2);
            const u32 off0 = hbase_off + ((c0 ^ qr) << 4);
            const u32 off1 = hbase_off + (((c0 + 1u) ^ qr) << 4);
            asm volatile("st.shared.v4.b32 [%0], {%1,%2,%3,%4};"
                :: "r"(sb + SM_H(0) + off0), "r"(hw[0]), "r"(hw[1]), "r"(hw[2]), "r"(hw[3]) : "memory");
            asm volatile("st.shared.v4.b32 [%0], {%1,%2,%3,%4};"
                :: "r"(sb + SM_H(0) + off1), "r"(hw[4]), "r"(hw[5]), "r"(hw[6]), "r"(hw[7]) : "memory");
        }

        int buf = 0;
        for (int ch = 0; ch < 8; ch++) {
            __syncthreads();
            const int nb = buf ^ 1;
            if (ch < 7) {
                const __half* ps = prow + (ch + 1) * 64;
                pf[0] = *(const uint4*)(ps);
                pf[1] = *(const uint4*)(ps + 8);
            }

            const u32 hH = sb + SM_H(buf);
            const u32 bB = sb + SM_BC(ch);
#pragma unroll
            for (int ks = 0; ks < 4; ks++) {
                u32 ah[4];
                {
                    int ra = wm * 16 + (l & 15);
                    u32 qa = ((u32)ra >> 3) & 3;
                    u32 chk = (((u32)(l >> 4) + 2u * ks) ^ qa) << 4;
                    ldm_x4(ah, hH + (u32)(ra * 144) + chk);
                }
#pragma unroll
                for (int p = 0; p < 4; p++) {
                    int rb = wn * 72 + p * 16 + (l & 7) + ((l >> 4) & 1) * 8;
                    u32 chunkf = 2u * ks + ((u32)(l >> 3) & 1u);
                    u32 bb[4];
                    ldm_x4(bb, bB + (u32)(rb << 7) + ((chunkf ^ ((u32)rb & 7u)) << 4));
#pragma unroll
                    for (int t = 0; t < 2; t++)
                        mma_f16(acc[p * 2 + t], ah, &bb[2 * t]);
                }
                {
                    int rb2 = 64 + (l & 7);
                    u32 chunkf = 2u * ks + ((u32)(l >> 3) & 1u);
                    u32 s2[2];
                    ldm_x2(s2, bB + (u32)(rb2 << 7) + ((chunkf ^ ((u32)rb2 & 7u)) << 4));
                    mma_f16(acc[8], ah, s2);
                }
            }

            if (ch < 7) {
                const float* ap = a_sm + (ch + 1) * 64 + quarter * 16;
                const __half2* ph = (const __half2*)pf;
                u32 hw[8];
#pragma unroll
                for (int i = 0; i < 8; i++) {
                    float2 p2 = __half22float2(ph[i]);
                    float x0 = fmaxf(p2.x + ap[2*i],     0.f);
                    float x1 = fmaxf(p2.y + ap[2*i + 1], 0.f);
                    hw[i] = h2u(__floats2half2_rn(x0, x1));
                }
                const u32 c0 = (u32)(quarter * 2);
                const u32 off0 = hbase_off + ((c0 ^ qr) << 4);
                const u32 off1 = hbase_off + (((c0 + 1u) ^ qr) << 4);
                asm volatile("st.shared.v4.b32 [%0], {%1,%2,%3,%4};"
                    :: "r"(sb + SM_H(nb) + off0), "r"(hw[0]), "r"(hw[1]), "r"(hw[2]), "r"(hw[3]) : "memory");
                asm volatile("st.shared.v4.b32 [%0], {%1,%2,%3,%4};"
                    :: "r"(sb + SM_H(nb) + off1), "r"(hw[4]), "r"(hw[5]), "r"(hw[6]), "r"(hw[7]) : "memory");
            }
            buf = nb;
        }

        const int g = l >> 2, tg = l & 3;
        const int i0 = ibase + wm * 16 + g;
        const int i1 = i0 + 8;
        const bool ok0 = i0 < cntb, ok1 = i1 < cntb;
        const int v0 = ok0 ? idx[b * VV + i0] : 0;
        const int v1 = ok1 ? idx[b * VV + i1] : 0;
#pragma unroll
        for (int nt = 0; nt < 9; nt++) {
            const int cbase = wn * 72 + nt * 8 + tg * 2;
#pragma unroll
            for (int q = 0; q < 2; q++) {
                const int col = cbase + q;
                if (col >= CC) continue;
                const float bias = __ldg(&b2[col]);
                if (ok0) sem[((size_t)b * CC + col) * VV + v0] = acc[nt][q] + bias;
                if (ok1) sem[((size_t)b * CC + col) * VV + v1] = acc[nt][2 + q] + bias;
            }
        }
    }
}

// ---------------------------------------------------------------------------
extern "C" void kernel_launch(void* const* d_in, const int* in_sizes, int n_in,
                              void* d_out, int out_size)
{
    const float* features  = (const float*)d_in[0];
    const float* W_contact = (const float*)d_in[3];
    const float* b_contact = (const float*)d_in[4];
    const float* Wv        = (const float*)d_in[7];
    const float* Wo        = (const float*)d_in[8];
    const float* W_cls     = (const float*)d_in[9];
    const float* b_cls     = (const float*)d_in[10];
    const float* pos_emb   = (const float*)d_in[11];
    const float* W_ft1     = (const float*)d_in[12];
    const float* b_ft1     = (const float*)d_in[13];
    const float* W_ft2     = (const float*)d_in[14];
    const float* b_ft2     = (const float*)d_in[15];

    float* out  = (float*)d_out;
    float* cont = out;                  // [16, 6890]
    float* sem  = out + BB * VV;        // [16, 133, 6890]

    float *part, *tmp, *att, *a;
    __half *Ph, *Bimg, *B1h;
    int *idx, *cnt;
    cudaGetSymbolAddress((void**)&part,  g_part);
    cudaGetSymbolAddress((void**)&tmp,   g_tmp);
    cudaGetSymbolAddress((void**)&att,   g_att);
    cudaGetSymbolAddress((void**)&a,     g_a);
    cudaGetSymbolAddress((void**)&Ph,    g_Ph);
    cudaGetSymbolAddress((void**)&idx,   g_idx);
    cudaGetSymbolAddress((void**)&cnt,   g_cnt);
    cudaGetSymbolAddress((void**)&Bimg,  g_Bimg);
    cudaGetSymbolAddress((void**)&B1h,   g_B1h);

    cudaFuncSetAttribute(k_sem_mma, cudaFuncAttributeMaxDynamicSharedMemorySize, SM_TOT);
    cudaFuncSetAttribute(k_front,   cudaFuncAttributeMaxDynamicSharedMemorySize, SMF_TOT);

    // ONE front-end launch: prep + zero + chain (with P overlapped) + P tail
    k_front<<<NPERS, 512, SMF_TOT>>>(features, W_contact, b_contact, Wv, Wo,
                                     W_cls, b_cls, W_ft1, b_ft1, W_ft2,
                                     pos_emb, part, tmp, att, a, cont,
                                     idx, cnt, Bimg, B1h, Ph,
                                     (float4*)sem, (BB * CC * VV) / 4);

    // persistent main GEMM
    k_sem_mma<<<NPERS, 512, SM_TOT>>>(a, Ph, Bimg, b_ft2, idx, cnt, sem);
}

// round 15
// speedup vs baseline: 1.1636x; 1.1636x over previous
#include <cuda_runtime.h>
#include <cuda_fp16.h>
#include <cuda_bf16.h>
#include <math.h>

// DECO decomposed (len-1 softmax == 1 → Wq/Wk/W_scene dead):
//   att  = (feat @ W_contact + b_c) @ Wv @ Wo            [16,1024]
//   cont = sigmoid(att @ W_cls + b_cls)                  [16,6890]
//   a    = att @ W_ft1[:1024] + b_ft1                    [16,512]
//   P    = pos_emb @ W_ft1[1024:]   (HMMA fp16 1-term, stored fp16)
//   sem[b,c,v] = mask * (relu(a[b]+P[v]) @ W_ft2 + b2)[c]
// R15: chain stages single-iteration (8-way split-K, 64-col blocks), 4 grid
// barriers, prep folded into s1, P tiles on idle CTAs + short tail; sem
// zeroing moved into k_sem prologue (overlapped with B-image cp.async).

#define BB   16
#define DF   1536
#define DD   1024
#define VV   6890
#define PDIM 256
#define HID  512
#define CC   133
#define NC   144
#define BROWS 136
#define NPERS 148
#define NPTILE 432          // 54 vb x 8 hb

typedef unsigned long long u64;
typedef unsigned int u32;

__device__ float g_part[8 * BB * DD];
__device__ float g_tmp [8 * BB * DD];
__device__ float g_att [8 * BB * DD];
__device__ float g_a   [8 * BB * HID];
__device__ __align__(16) __half g_Ph[VV * HID];
__device__ int   g_idx [BB * VV];
__device__ int   g_cnt [BB];
__device__ __align__(16) __half g_Bimg[8 * BROWS * 64];
__device__ __align__(16) __half g_B1h[4 * 512 * 64];
__device__ int   g_bar_arrive;
__device__ unsigned int g_bar_gen;

__device__ __forceinline__ u64 pk2(float lo, float hi) {
    u64 r; asm("mov.b64 %0, {%1, %2};" : "=l"(r) : "f"(lo), "f"(hi)); return r;
}
__device__ __forceinline__ void upk2(u64 v, float& lo, float& hi) {
    asm("mov.b64 {%0, %1}, %2;" : "=f"(lo), "=f"(hi) : "l"(v));
}
__device__ __forceinline__ u64 ffma2(u64 a, u64 b, u64 c) {
    u64 d; asm("fma.rn.f32x2 %0, %1, %2, %3;" : "=l"(d) : "l"(a), "l"(b), "l"(c));
    return d;
}
__device__ __forceinline__ u32 smem_u32(const void* p) {
    u32 a; asm("{ .reg .u64 t; cvta.to.shared.u64 t, %1; cvt.u32.u64 %0, t; }"
               : "=r"(a) : "l"(p));
    return a;
}
__device__ __forceinline__ void ldm_x4(u32* r, u32 addr) {
    asm volatile("ldmatrix.sync.aligned.m8n8.x4.shared.b16 {%0,%1,%2,%3}, [%4];"
        : "=r"(r[0]), "=r"(r[1]), "=r"(r[2]), "=r"(r[3]) : "r"(addr));
}
__device__ __forceinline__ void ldm_x2(u32* r, u32 addr) {
    asm volatile("ldmatrix.sync.aligned.m8n8.x2.shared.b16 {%0,%1}, [%2];"
        : "=r"(r[0]), "=r"(r[1]) : "r"(addr));
}
__device__ __forceinline__ void mma_f16(float* d, const u32* a, const u32* b) {
    asm volatile("mma.sync.aligned.m16n8k16.row.col.f32.f16.f16.f32 "
        "{%0,%1,%2,%3}, {%4,%5,%6,%7}, {%8,%9}, {%0,%1,%2,%3};"
        : "+f"(d[0]), "+f"(d[1]), "+f"(d[2]), "+f"(d[3])
        : "r"(a[0]), "r"(a[1]), "r"(a[2]), "r"(a[3]), "r"(b[0]), "r"(b[1]));
}
__device__ __forceinline__ u32 h2u(__half2 h) {
    u32 r; asm("mov.b32 %0, %1;" : "=r"(r) : "r"(*(u32*)&h)); return r;
}
__device__ __forceinline__ void cpasync16(u32 dst, const void* src) {
    asm volatile("cp.async.cg.shared.global [%0], [%1], 16;"
                 :: "r"(dst), "l"(src) : "memory");
}
__device__ __forceinline__ void cpasync_commit() {
    asm volatile("cp.async.commit_group;" ::: "memory");
}
__device__ __forceinline__ void cpasync_wait0() {
    asm volatile("cp.async.wait_group 0;" ::: "memory");
}

__device__ __forceinline__ void grid_bar() {
    __syncthreads();
    if (threadIdx.x == 0) {
        __threadfence();
        unsigned gen = atomicAdd(&g_bar_gen, 0u);
        int a = atomicAdd(&g_bar_arrive, 1);
        if (a == NPERS - 1) {
            g_bar_arrive = 0;
            __threadfence();
            atomicAdd(&g_bar_gen, 1u);
        } else {
            while (atomicAdd(&g_bar_gen, 0u) == gen) {}
        }
        __threadfence();
    }
    __syncthreads();
}

// k_sem smem layout (bytes)
#define SM_AS     0
#define SM_H(bf)  (2048 + (bf) * 18432)
#define SM_BALL   38912
#define SM_BC(ch) (SM_BALL + (ch) * 17408)
#define SM_TOT    178176
// k_front smem views: skinny64 (in_s 192*18 + red 8*1088), cont (in_s 128*18 +
// red 16*1024), ptile (HH 16KB | B 8KB)
#define SMF_TOT   122880
#define SMP_HH 0
#define SMP_B  16384

// ---------------------------------------------------------------------------
// Device fn: single-iteration split-K skinny GEMM vblock.
// 512 thr = 64 cols x 8 K-slices; kspan k-range staged once.
// ---------------------------------------------------------------------------
__device__ void skinny64_dev(const float* __restrict__ in,
                             const float* __restrict__ W,
                             const float* __restrict__ bias,
                             float* __restrict__ out,
                             int K, int N, int nsum, int colb, int ky,
                             int kspan, float* in_s, float* red)
{
    const int tid = threadIdx.x;
    const int col = tid & 63;
    const int slc = tid >> 6;
    const int colg = colb * 64 + col;
    const int kbase = ky * kspan;
    const int kper = kspan >> 3;

    // stage in (sum of nsum partials), transposed [k][b]
    for (int e = tid; e < kspan * 16; e += 512) {
        int b = e / kspan;
        int k = e - b * kspan;
        float s = 0.f;
        for (int sc = 0; sc < nsum; sc++)
            s += in[(size_t)sc * BB * K + b * K + kbase + k];
        in_s[k * 18 + b] = s;
    }
    __syncthreads();

    u64 acc2[8];
#pragma unroll
    for (int m = 0; m < 8; m++) acc2[m] = 0ull;

    for (int kk = 0; kk < kper; kk++) {
        int k = slc * kper + kk;
        float w = W[(size_t)(kbase + k) * N + colg];
        u64 w2 = pk2(w, w);
        const u64* ip = (const u64*)&in_s[k * 18];
#pragma unroll
        for (int m = 0; m < 8; m++)
            acc2[m] = ffma2(ip[m], w2, acc2[m]);
    }
    // padded reduction buffer: red[slc*1088 + col*17 + b]
    float* rp = &red[slc * 1088 + col * 17];
#pragma unroll
    for (int m = 0; m < 8; m++) {
        float lo, hi; upk2(acc2[m], lo, hi);
        rp[2 * m] = lo; rp[2 * m + 1] = hi;
    }
    __syncthreads();
    for (int o = tid; o < 1024; o += 512) {
        int c = o >> 4, b = o & 15;
        float s = 0.f;
#pragma unroll
        for (int sl = 0; sl < 8; sl++) s += red[sl * 1088 + c * 17 + b];
        float bb = (bias && ky == 0) ? bias[colb * 64 + c] : 0.f;
        out[(size_t)ky * BB * N + b * N + colb * 64 + c] = s + bb;
    }
    __syncthreads();
}

// ---------------------------------------------------------------------------
// Device fn: cont vblock (64 cols), sums 8 att partials.
// ---------------------------------------------------------------------------
__device__ void cont_dev(const float* __restrict__ att,
                         const float* __restrict__ Wc,
                         const float* __restrict__ bc,
                         float* __restrict__ out, int vb,
                         float* in_s, float* red)
{
    const int tid = threadIdx.x;
    const int cp  = tid & 31;
    const int slc = tid >> 5;
    const int col0 = vb * 64 + 2 * cp;
    const int colc = col0 <= VV - 2 ? col0 : VV - 2;

    u64 acc[2][8];
#pragma unroll
    for (int j = 0; j < 2; j++)
#pragma unroll
        for (int m = 0; m < 8; m++) acc[j][m] = 0ull;

    for (int k0 = 0; k0 < DD; k0 += 128) {
        __syncthreads();
#pragma unroll
        for (int i = 0; i < 4; i++) {
            int e = tid + 512 * i;
            int b = e >> 7, k = e & 127;
            float s = 0.f;
#pragma unroll
            for (int sc = 0; sc < 8; sc++)
                s += att[(size_t)sc * BB * DD + b * DD + k0 + k];
            in_s[k * 18 + b] = s;
        }
        __syncthreads();
#pragma unroll
        for (int kk = 0; kk < 8; kk++) {
            int k = slc * 8 + kk;
            float2 w = *(const float2*)&Wc[(size_t)(k0 + k) * VV + colc];
            u64 w0 = pk2(w.x, w.x), w1 = pk2(w.y, w.y);
            const u64* ip = (const u64*)&in_s[k * 18];
#pragma unroll
            for (int m = 0; m < 8; m++) {
                acc[0][m] = ffma2(ip[m], w0, acc[0][m]);
                acc[1][m] = ffma2(ip[m], w1, acc[1][m]);
            }
        }
    }
#pragma unroll
    for (int j = 0; j < 2; j++) {
        float* rp = &red[slc * 1024 + (2 * cp + j) * 16];
#pragma unroll
        for (int m = 0; m < 8; m++) {
            float lo, hi; upk2(acc[j][m], lo, hi);
            rp[2 * m] = lo; rp[2 * m + 1] = hi;
        }
    }
    __syncthreads();
    for (int o = tid; o < 1024; o += 512) {
        int c = o >> 4, b = o & 15;
        float s = 0.f;
#pragma unroll
        for (int sl = 0; sl < 16; sl++) s += red[sl * 1024 + c * 16 + b];
        int cg = vb * 64 + c;
        if (cg < VV)
            out[b * VV + cg] = 1.f / (1.f + expf(-(s + bc[cg])));
    }
    __syncthreads();
}

// ---------------------------------------------------------------------------
// Device fn: order-preserving compaction for batch b.
// ---------------------------------------------------------------------------
__device__ void compact_dev(const float* __restrict__ cont,
                            int* __restrict__ idx, int* __restrict__ cnt,
                            int b)
{
    const int tid = threadIdx.x;
    const int lane = tid & 31, wrp = tid >> 5;
    __shared__ int wexc[16];
    __shared__ int s_base, s_tot;
    if (tid == 0) s_base = 0;
    __syncthreads();
    for (int v0 = 0; v0 < VV; v0 += 512) {
        int v = v0 + tid;
        int m = (v < VV) && (cont[b * VV + v] > 0.5f);
        unsigned bal = __ballot_sync(0xffffffffu, m);
        int wsum = __popc(bal);
        int pw = __popc(bal & ((1u << lane) - 1u));
        if (lane == 0) wexc[wrp] = wsum;
        __syncthreads();
        if (tid < 16) {
            int sv = wexc[tid];
            int e = sv;
#pragma unroll
            for (int d = 1; d < 16; d <<= 1) {
                int t = __shfl_up_sync(0xffffu, e, d);
                if (tid >= d) e += t;
            }
            wexc[tid] = e - sv;
            if (tid == 15) s_tot = e;
        }
        __syncthreads();
        int pos = s_base + wexc[wrp] + pw;
        if (v < VV && m) idx[b * VV + pos] = v;
        __syncthreads();
        if (tid == 0) s_base += s_tot;
        __syncthreads();
    }
    if (tid == 0) cnt[b] = s_base;
}

// ---------------------------------------------------------------------------
// Device fn: one P tile (128 v x 64 h), K=256, fp16 1-TERM.
// ---------------------------------------------------------------------------
__device__ void ptile_dev(const float* __restrict__ pos,
                          const __half* __restrict__ B1h,
                          __half* __restrict__ Ph,
                          int tile, char* smem, u32 sb)
{
    const int vb = tile >> 3, hb = tile & 7;
    const int vbase = vb * 128, hbase = hb * 64;
    const int tid = threadIdx.x;
    const int wid = tid >> 5, l = tid & 31;
    const int wm = wid & 7, wn = wid >> 3;
    const int r = tid & 127, quarter = tid >> 7;
    const int v = vbase + r;
    const int vc = v < VV ? v : VV - 1;
    const float* __restrict__ prow = pos + (size_t)vc * PDIM + quarter * 16;

    float acc[4][4];
#pragma unroll
    for (int j = 0; j < 4; j++)
#pragma unroll
        for (int q = 0; q < 4; q++) acc[j][q] = 0.f;

    for (int ch = 0; ch < 4; ch++) {
        __syncthreads();
        {
            float x[16];
#pragma unroll
            for (int q = 0; q < 4; q++) {
                float4 p4 = *(const float4*)(prow + ch * 64 + 4 * q);
                x[4*q+0] = p4.x; x[4*q+1] = p4.y; x[4*q+2] = p4.z; x[4*q+3] = p4.w;
            }
            u32 hw[8];
#pragma unroll
            for (int i = 0; i < 8; i++)
                hw[i] = h2u(__floats2half2_rn(x[2*i], x[2*i+1]));
            const u32 c0 = (u32)(quarter * 2);
            const u32 q7 = (u32)r & 7u;
            const u32 off0 = (u32)(r << 7) + ((c0 ^ q7) << 4);
            const u32 off1 = (u32)(r << 7) + (((c0 + 1u) ^ q7) << 4);
            asm volatile("st.shared.v4.b32 [%0], {%1,%2,%3,%4};"
                :: "r"(sb + SMP_HH + off0), "r"(hw[0]), "r"(hw[1]), "r"(hw[2]), "r"(hw[3]) : "memory");
            asm volatile("st.shared.v4.b32 [%0], {%1,%2,%3,%4};"
                :: "r"(sb + SMP_HH + off1), "r"(hw[4]), "r"(hw[5]), "r"(hw[6]), "r"(hw[7]) : "memory");
        }
        ((uint4*)(smem + SMP_B))[tid] =
            ((const uint4*)(B1h + (size_t)ch * 32768 + (size_t)hbase * 64))[tid];
        __syncthreads();
#pragma unroll
        for (int ks = 0; ks < 4; ks++) {
            u32 ah[4];
            {
                int ra = wm * 16 + (l & 15);
                u32 chk = (((u32)(l >> 4) + 2u * ks) ^ ((u32)ra & 7u)) << 4;
                ldm_x4(ah, sb + SMP_HH + (u32)(ra << 7) + chk);
            }
#pragma unroll
            for (int p = 0; p < 2; p++) {
                int rb = wn * 32 + p * 16 + (l & 7) + ((l >> 4) & 1) * 8;
                u32 cf = 2u * ks + ((u32)(l >> 3) & 1u);
                u32 bb[4];
                ldm_x4(bb, sb + SMP_B + (u32)(rb << 7) + ((cf ^ ((u32)rb & 7u)) << 4));
#pragma unroll
                for (int t = 0; t < 2; t++)
                    mma_f16(acc[p * 2 + t], ah, &bb[2 * t]);
            }
        }
    }
    __syncthreads();

    const int g = l >> 2, tg = l & 3;
    const int i0 = vbase + wm * 16 + g;
    const int i1 = i0 + 8;
#pragma unroll
    for (int nt = 0; nt < 4; nt++) {
        const int col = hbase + wn * 32 + nt * 8 + tg * 2;
        if (i0 < VV)
            *(__half2*)&Ph[(size_t)i0 * HID + col]
                = __floats2half2_rn(acc[nt][0], acc[nt][1]);
        if (i1 < VV)
            *(__half2*)&Ph[(size_t)i1 * HID + col]
                = __floats2half2_rn(acc[nt][2], acc[nt][3]);
    }
}

__device__ __forceinline__ void ptile1(const float* pos, const __half* B1h,
                                       __half* Ph, int t, char* smem, u32 sb)
{
    if (t >= 0 && t < NPTILE) ptile_dev(pos, B1h, Ph, t, smem, sb);
}

// ---------------------------------------------------------------------------
// MEGA front-end: s1(+prep) | s2 | s3 | s4 | s5 | P tail. 4 grid barriers.
// ---------------------------------------------------------------------------
__global__ void __launch_bounds__(512, 1)
k_front(const float* __restrict__ features,
        const float* __restrict__ W_contact, const float* __restrict__ b_contact,
        const float* __restrict__ Wv, const float* __restrict__ Wo,
        const float* __restrict__ W_cls, const float* __restrict__ b_cls,
        const float* __restrict__ W_ft1, const float* __restrict__ b_ft1,
        const float* __restrict__ W_ft2, const float* __restrict__ pos,
        float* __restrict__ part, float* __restrict__ tmp,
        float* __restrict__ att, float* __restrict__ a,
        float* __restrict__ cont, int* __restrict__ idx, int* __restrict__ cnt,
        __half* __restrict__ Bimg, __half* __restrict__ B1h,
        __half* __restrict__ Ph)
{
    extern __shared__ char smemc[];
    float* in_s = (float*)smemc;                       // up to 192*18
    float* red  = (float*)(smemc + 192 * 18 * 4);      // up to 16*1024
    const u32 sb = smem_u32(smemc);
    const int bid = blockIdx.x;
    const int tid = threadIdx.x;

    // s1: chain stage 1 (128 CTAs) + weight-image prep on idle CTAs
    if (bid < 128) {
        skinny64_dev(features, W_contact, b_contact, part, DF, DD, 1,
                     bid & 15, bid >> 4, 192, in_s, red);
    } else if (bid < 136) {
        const int img = bid - 128;
        for (int e = tid; e < BROWS * 64; e += 512) {
            int n = e >> 6, k = e & 63;
            float w = (n < CC) ? W_ft2[(size_t)(img * 64 + k) * CC + n] : 0.f;
            int off = (n << 6) + (((k >> 3) ^ (n & 7)) << 3) + (k & 7);
            Bimg[(size_t)img * (BROWS * 64) + off] = __float2half_rn(w);
        }
    } else if (bid < 140) {
        const int ch = bid - 136;
        for (int e = tid; e < 512 * 64; e += 512) {
            int n = e >> 6, k = e & 63;
            float w = W_ft1[(size_t)(DD + ch * 64 + k) * HID + n];
            int off = (n << 6) + (((k >> 3) ^ (n & 7)) << 3) + (k & 7);
            B1h[(size_t)ch * (512 * 64) + off] = __float2half_rn(w);
        }
    }
    grid_bar();
    // s2
    if (bid < 128)
        skinny64_dev(part, Wv, nullptr, tmp, DD, DD, 8, bid & 15, bid >> 4,
                     128, in_s, red);
    else
        ptile1(pos, B1h, Ph, bid - 128, smemc, sb);
    grid_bar();
    // s3
    if (bid < 128)
        skinny64_dev(tmp, Wo, nullptr, att, DD, DD, 8, bid & 15, bid >> 4,
                     128, in_s, red);
    else
        ptile1(pos, B1h, Ph, 20 + bid - 128, smemc, sb);
    grid_bar();
    // s4: cont (108) + ptiles (40)
    if (bid < 108)
        cont_dev(att, W_cls, b_cls, cont, bid, in_s, red);
    else
        ptile1(pos, B1h, Ph, 40 + bid - 108, smemc, sb);
    grid_bar();
    // s5: a (64) + compact (16) + ptiles (68); no barrier after
    if (bid < 64)
        skinny64_dev(att, W_ft1, b_ft1, a, DD, HID, 8, bid & 7, bid >> 3,
                     128, in_s, red);
    else if (bid < 80)
        compact_dev(cont, idx, cnt, bid - 64);
    else
        ptile1(pos, B1h, Ph, 80 + bid - 80, smemc, sb);
    // P tail: tiles 148..431
    ptile1(pos, B1h, Ph, 148 + bid, smemc, sb);
    ptile1(pos, B1h, Ph, 296 + bid, smemc, sb);
}

// ---------------------------------------------------------------------------
// PERSISTENT main GEMM: fp16 1-term, 512 thr (8m x 2n), P fp16, all B chunks
// smem-resident, fused scattered epilogue. Prologue zeroes sem (overlapped
// with B-image cp.async) + one grid barrier.
// ---------------------------------------------------------------------------
__global__ void __launch_bounds__(512, 1)
k_sem_mma(const float* __restrict__ A8,
          const __half* __restrict__ Ph,
          const __half* __restrict__ Bimg,
          const float* __restrict__ b2,
          const int* __restrict__ idx,
          const int* __restrict__ cnt,
          float* __restrict__ sem)
{
    extern __shared__ char smem[];
    const u32 sb = smem_u32(smem);
    const int tid = threadIdx.x;
    const int wid = tid >> 5;
    const int l   = tid & 31;
    const int wm = wid & 7;
    const int wn = wid >> 3;
    const int r = tid & 127;
    const int quarter = tid >> 7;
    const u32 qr = ((u32)r >> 3) & 3;
    const u32 hbase_off = (u32)(r * 144);

    // B images via cp.async; zero sem concurrently; then grid barrier
    {
        const char* srcB = (const char*)(Bimg);
        u32 dstB = sb + SM_BALL;
        for (int e = tid; e < 8 * 1088; e += 512)
            cpasync16(dstB + e * 16, srcB + e * 16);
        cpasync_commit();
    }
    {
        float4* z = (float4*)sem;
        const int n4 = (BB * CC * VV) / 4;
        for (int i = blockIdx.x * 512 + tid; i < n4; i += NPERS * 512)
            z[i] = make_float4(0.f, 0.f, 0.f, 0.f);
    }
    cpasync_wait0();
    grid_bar();

    int offv[17];
    offv[0] = 0;
#pragma unroll
    for (int b = 0; b < 16; b++)
        offv[b + 1] = offv[b] + ((cnt[b] + 127) >> 7);
    const int total = offv[16];

    float* a_sm = (float*)(smem + SM_AS);

    for (int w = blockIdx.x; w < total; w += NPERS) {
        int b = 0;
#pragma unroll
        for (int t = 0; t < 15; t++) if (w >= offv[b + 1]) b++;
        const int cntb = cnt[b];
        const int ibase = (w - offv[b]) << 7;

        {
            float s = 0.f;
#pragma unroll
            for (int sc = 0; sc < 8; sc++)
                s += A8[(size_t)sc * BB * HID + b * HID + tid];
            a_sm[tid] = s;
        }

        const int ig = ibase + r;
        const int vrow = idx[b * VV + (ig < cntb ? ig : cntb - 1)];
        const __half* __restrict__ prow = Ph + (size_t)vrow * HID + quarter * 16;

        float acc[9][4];
#pragma unroll
        for (int j = 0; j < 9; j++)
#pragma unroll
            for (int q = 0; q < 4; q++) acc[j][q] = 0.f;

        uint4 pf[2];
        pf[0] = *(const uint4*)(prow);
        pf[1] = *(const uint4*)(prow + 8);
        __syncthreads();

        {
            const float* ap = a_sm + quarter * 16;
            const __half2* ph = (const __half2*)pf;
            u32 hw[8];
#pragma unroll
            for (int i = 0; i < 8; i++) {
                float2 p2 = __half22float2(ph[i]);
                float x0 = fmaxf(p2.x + ap[2*i],     0.f);
                float x1 = fmaxf(p2.y + ap[2*i + 1], 0.f);
                hw[i] = h2u(__floats2half2_rn(x0, x1));
            }
            const u32 c0 = (u32)(quarter * 2);
            const u32 off0 = hbase_off + ((c0 ^ qr) << 4);
            const u32 off1 = hbase_off + (((c0 + 1u) ^ qr) << 4);
            asm volatile("st.shared.v4.b32 [%0], {%1,%2,%3,%4};"
                :: "r"(sb + SM_H(0) + off0), "r"(hw[0]), "r"(hw[1]), "r"(hw[2]), "r"(hw[3]) : "memory");
            asm volatile("st.shared.v4.b32 [%0], {%1,%2,%3,%4};"
                :: "r"(sb + SM_H(0) + off1), "r"(hw[4]), "r"(hw[5]), "r"(hw[6]), "r"(hw[7]) : "memory");
        }

        int buf = 0;
        for (int ch = 0; ch < 8; ch++) {
            __syncthreads();
            const int nb = buf ^ 1;
            if (ch < 7) {
                const __half* ps = prow + (ch + 1) * 64;
                pf[0] = *(const uint4*)(ps);
                pf[1] = *(const uint4*)(ps + 8);
            }

            const u32 hH = sb + SM_H(buf);
            const u32 bB = sb + SM_BC(ch);
#pragma unroll
            for (int ks = 0; ks < 4; ks++) {
                u32 ah[4];
                {
                    int ra = wm * 16 + (l & 15);
                    u32 qa = ((u32)ra >> 3) & 3;
                    u32 chk = (((u32)(l >> 4) + 2u * ks) ^ qa) << 4;
                    ldm_x4(ah, hH + (u32)(ra * 144) + chk);
                }
#pragma unroll
                for (int p = 0; p < 4; p++) {
                    int rb = wn * 72 + p * 16 + (l & 7) + ((l >> 4) & 1) * 8;
                    u32 chunkf = 2u * ks + ((u32)(l >> 3) & 1u);
                    u32 bb[4];
                    ldm_x4(bb, bB + (u32)(rb << 7) + ((chunkf ^ ((u32)rb & 7u)) << 4));
#pragma unroll
                    for (int t = 0; t < 2; t++)
                        mma_f16(acc[p * 2 + t], ah, &bb[2 * t]);
                }
                {
                    int rb2 = 64 + (l & 7);
                    u32 chunkf = 2u * ks + ((u32)(l >> 3) & 1u);
                    u32 s2[2];
                    ldm_x2(s2, bB + (u32)(rb2 << 7) + ((chunkf ^ ((u32)rb2 & 7u)) << 4));
                    mma_f16(acc[8], ah, s2);
                }
            }

            if (ch < 7) {
                const float* ap = a_sm + (ch + 1) * 64 + quarter * 16;
                const __half2* ph = (const __half2*)pf;
                u32 hw[8];
#pragma unroll
                for (int i = 0; i < 8; i++) {
                    float2 p2 = __half22float2(ph[i]);
                    float x0 = fmaxf(p2.x + ap[2*i],     0.f);
                    float x1 = fmaxf(p2.y + ap[2*i + 1], 0.f);
                    hw[i] = h2u(__floats2half2_rn(x0, x1));
                }
                const u32 c0 = (u32)(quarter * 2);
                const u32 off0 = hbase_off + ((c0 ^ qr) << 4);
                const u32 off1 = hbase_off + (((c0 + 1u) ^ qr) << 4);
                asm volatile("st.shared.v4.b32 [%0], {%1,%2,%3,%4};"
                    :: "r"(sb + SM_H(nb) + off0), "r"(hw[0]), "r"(hw[1]), "r"(hw[2]), "r"(hw[3]) : "memory");
                asm volatile("st.shared.v4.b32 [%0], {%1,%2,%3,%4};"
                    :: "r"(sb + SM_H(nb) + off1), "r"(hw[4]), "r"(hw[5]), "r"(hw[6]), "r"(hw[7]) : "memory");
            }
            buf = nb;
        }

        const int g = l >> 2, tg = l & 3;
        const int i0 = ibase + wm * 16 + g;
        const int i1 = i0 + 8;
        const bool ok0 = i0 < cntb, ok1 = i1 < cntb;
        const int v0 = ok0 ? idx[b * VV + i0] : 0;
        const int v1 = ok1 ? idx[b * VV + i1] : 0;
#pragma unroll
        for (int nt = 0; nt < 9; nt++) {
            const int cbase = wn * 72 + nt * 8 + tg * 2;
#pragma unroll
            for (int q = 0; q < 2; q++) {
                const int col = cbase + q;
                if (col >= CC) continue;
                const float bias = __ldg(&b2[col]);
                if (ok0) sem[((size_t)b * CC + col) * VV + v0] = acc[nt][q] + bias;
                if (ok1) sem[((size_t)b * CC + col) * VV + v1] = acc[nt][2 + q] + bias;
            }
        }
    }
}

// ---------------------------------------------------------------------------
extern "C" void kernel_launch(void* const* d_in, const int* in_sizes, int n_in,
                              void* d_out, int out_size)
{
    const float* features  = (const float*)d_in[0];
    const float* W_contact = (const float*)d_in[3];
    const float* b_contact = (const float*)d_in[4];
    const float* Wv        = (const float*)d_in[7];
    const float* Wo        = (const float*)d_in[8];
    const float* W_cls     = (const float*)d_in[9];
    const float* b_cls     = (const float*)d_in[10];
    const float* pos_emb   = (const float*)d_in[11];
    const float* W_ft1     = (const float*)d_in[12];
    const float* b_ft1     = (const float*)d_in[13];
    const float* W_ft2     = (const float*)d_in[14];
    const float* b_ft2     = (const float*)d_in[15];

    float* out  = (float*)d_out;
    float* cont = out;                  // [16, 6890]
    float* sem  = out + BB * VV;        // [16, 133, 6890]

    float *part, *tmp, *att, *a;
    __half *Ph, *Bimg, *B1h;
    int *idx, *cnt;
    cudaGetSymbolAddress((void**)&part,  g_part);
    cudaGetSymbolAddress((void**)&tmp,   g_tmp);
    cudaGetSymbolAddress((void**)&att,   g_att);
    cudaGetSymbolAddress((void**)&a,     g_a);
    cudaGetSymbolAddress((void**)&Ph,    g_Ph);
    cudaGetSymbolAddress((void**)&idx,   g_idx);
    cudaGetSymbolAddress((void**)&cnt,   g_cnt);
    cudaGetSymbolAddress((void**)&Bimg,  g_Bimg);
    cudaGetSymbolAddress((void**)&B1h,   g_B1h);

    cudaFuncSetAttribute(k_sem_mma, cudaFuncAttributeMaxDynamicSharedMemorySize, SM_TOT);
    cudaFuncSetAttribute(k_front,   cudaFuncAttributeMaxDynamicSharedMemorySize, SMF_TOT);

    // front-end: prep + chain (single-iteration stages) + P overlapped/tail
    k_front<<<NPERS, 512, SMF_TOT>>>(features, W_contact, b_contact, Wv, Wo,
                                     W_cls, b_cls, W_ft1, b_ft1, W_ft2,
                                     pos_emb, part, tmp, att, a, cont,
                                     idx, cnt, Bimg, B1h, Ph);

    // main GEMM (zeroes sem in prologue, overlapped with B-image load)
    k_sem_mma<<<NPERS, 512, SM_TOT>>>(a, Ph, Bimg, b_ft2, idx, cnt, sem);
}

// round 16
// speedup vs baseline: 1.1983x; 1.0298x over previous
#include <cuda_runtime.h>
#include <cuda_fp16.h>
#include <cuda_bf16.h>
#include <math.h>

// DECO decomposed (len-1 softmax == 1 → Wq/Wk/W_scene dead):
//   att  = (feat @ W_contact + b_c) @ Wv @ Wo            [16,1024]
//   cont = sigmoid(att @ W_cls + b_cls)                  [16,6890]
//   a    = att @ W_ft1[:1024] + b_ft1                    [16,512]
//   P    = pos_emb @ W_ft1[1024:]   (HMMA fp16 1-term, stored fp16)
//   sem[b,c,v] = mask * (relu(a[b]+P[v]) @ W_ft2 + b2)[c]
// R16: k_sem -> 64-row tiles, 256 thr/CTA, 2 CTAs/SM (grid 296), B chunks
// double-buffered via cp.async. Front-end chain unchanged (R15).

#define BB   16
#define DF   1536
#define DD   1024
#define VV   6890
#define PDIM 256
#define HID  512
#define CC   133
#define NC   144
#define BROWS 136
#define NPERS 148
#define NSEM  296
#define NPTILE 432

typedef unsigned long long u64;
typedef unsigned int u32;

__device__ float g_part[8 * BB * DD];
__device__ float g_tmp [8 * BB * DD];
__device__ float g_att [8 * BB * DD];
__device__ float g_a   [8 * BB * HID];
__device__ __align__(16) __half g_Ph[VV * HID];
__device__ int   g_idx [BB * VV];
__device__ int   g_cnt [BB];
__device__ __align__(16) __half g_Bimg[8 * BROWS * 64];
__device__ __align__(16) __half g_B1h[4 * 512 * 64];
__device__ int   g_bar_arrive;
__device__ unsigned int g_bar_gen;

__device__ __forceinline__ u64 pk2(float lo, float hi) {
    u64 r; asm("mov.b64 %0, {%1, %2};" : "=l"(r) : "f"(lo), "f"(hi)); return r;
}
__device__ __forceinline__ void upk2(u64 v, float& lo, float& hi) {
    asm("mov.b64 {%0, %1}, %2;" : "=f"(lo), "=f"(hi) : "l"(v));
}
__device__ __forceinline__ u64 ffma2(u64 a, u64 b, u64 c) {
    u64 d; asm("fma.rn.f32x2 %0, %1, %2, %3;" : "=l"(d) : "l"(a), "l"(b), "l"(c));
    return d;
}
__device__ __forceinline__ u32 smem_u32(const void* p) {
    u32 a; asm("{ .reg .u64 t; cvta.to.shared.u64 t, %1; cvt.u32.u64 %0, t; }"
               : "=r"(a) : "l"(p));
    return a;
}
__device__ __forceinline__ void ldm_x4(u32* r, u32 addr) {
    asm volatile("ldmatrix.sync.aligned.m8n8.x4.shared.b16 {%0,%1,%2,%3}, [%4];"
        : "=r"(r[0]), "=r"(r[1]), "=r"(r[2]), "=r"(r[3]) : "r"(addr));
}
__device__ __forceinline__ void ldm_x2(u32* r, u32 addr) {
    asm volatile("ldmatrix.sync.aligned.m8n8.x2.shared.b16 {%0,%1}, [%2];"
        : "=r"(r[0]), "=r"(r[1]) : "r"(addr));
}
__device__ __forceinline__ void mma_f16(float* d, const u32* a, const u32* b) {
    asm volatile("mma.sync.aligned.m16n8k16.row.col.f32.f16.f16.f32 "
        "{%0,%1,%2,%3}, {%4,%5,%6,%7}, {%8,%9}, {%0,%1,%2,%3};"
        : "+f"(d[0]), "+f"(d[1]), "+f"(d[2]), "+f"(d[3])
        : "r"(a[0]), "r"(a[1]), "r"(a[2]), "r"(a[3]), "r"(b[0]), "r"(b[1]));
}
__device__ __forceinline__ u32 h2u(__half2 h) {
    u32 r; asm("mov.b32 %0, %1;" : "=r"(r) : "r"(*(u32*)&h)); return r;
}
__device__ __forceinline__ void cpasync16(u32 dst, const void* src) {
    asm volatile("cp.async.cg.shared.global [%0], [%1], 16;"
                 :: "r"(dst), "l"(src) : "memory");
}
__device__ __forceinline__ void cpasync_commit() {
    asm volatile("cp.async.commit_group;" ::: "memory");
}
__device__ __forceinline__ void cpasync_wait0() {
    asm volatile("cp.async.wait_group 0;" ::: "memory");
}

__device__ __forceinline__ void grid_bar(int nctas) {
    __syncthreads();
    if (threadIdx.x == 0) {
        __threadfence();
        unsigned gen = atomicAdd(&g_bar_gen, 0u);
        int a = atomicAdd(&g_bar_arrive, 1);
        if (a == nctas - 1) {
            g_bar_arrive = 0;
            __threadfence();
            atomicAdd(&g_bar_gen, 1u);
        } else {
            while (atomicAdd(&g_bar_gen, 0u) == gen) {}
        }
        __threadfence();
    }
    __syncthreads();
}

// k_sem smem layout (bytes), 256 thr, 64-row tiles
#define S2_AS    0                       // 512 f32 = 2048
#define S2_H(bf) (2048 + (bf) * 9216)    // 64 x 144 B
#define S2_B(bf) (20480 + (bf) * 17408)  // 136 x 128 B
#define S2_TOT   55296
// k_front smem views
#define SMF_TOT  122880
#define SMP_HH 0
#define SMP_B  16384

// ---------------------------------------------------------------------------
// Device fn: single-iteration split-K skinny GEMM vblock (512 thr).
// ---------------------------------------------------------------------------
__device__ void skinny64_dev(const float* __restrict__ in,
                             const float* __restrict__ W,
                             const float* __restrict__ bias,
                             float* __restrict__ out,
                             int K, int N, int nsum, int colb, int ky,
                             int kspan, float* in_s, float* red)
{
    const int tid = threadIdx.x;
    const int col = tid & 63;
    const int slc = tid >> 6;
    const int colg = colb * 64 + col;
    const int kbase = ky * kspan;
    const int kper = kspan >> 3;

    for (int e = tid; e < kspan * 16; e += 512) {
        int b = e / kspan;
        int k = e - b * kspan;
        float s = 0.f;
        for (int sc = 0; sc < nsum; sc++)
            s += in[(size_t)sc * BB * K + b * K + kbase + k];
        in_s[k * 18 + b] = s;
    }
    __syncthreads();

    u64 acc2[8];
#pragma unroll
    for (int m = 0; m < 8; m++) acc2[m] = 0ull;

    for (int kk = 0; kk < kper; kk++) {
        int k = slc * kper + kk;
        float w = W[(size_t)(kbase + k) * N + colg];
        u64 w2 = pk2(w, w);
        const u64* ip = (const u64*)&in_s[k * 18];
#pragma unroll
        for (int m = 0; m < 8; m++)
            acc2[m] = ffma2(ip[m], w2, acc2[m]);
    }
    float* rp = &red[slc * 1088 + col * 17];
#pragma unroll
    for (int m = 0; m < 8; m++) {
        float lo, hi; upk2(acc2[m], lo, hi);
        rp[2 * m] = lo; rp[2 * m + 1] = hi;
    }
    __syncthreads();
    for (int o = tid; o < 1024; o += 512) {
        int c = o >> 4, b = o & 15;
        float s = 0.f;
#pragma unroll
        for (int sl = 0; sl < 8; sl++) s += red[sl * 1088 + c * 17 + b];
        float bb = (bias && ky == 0) ? bias[colb * 64 + c] : 0.f;
        out[(size_t)ky * BB * N + b * N + colb * 64 + c] = s + bb;
    }
    __syncthreads();
}

// ---------------------------------------------------------------------------
// Device fn: cont vblock (64 cols), sums 8 att partials.
// ---------------------------------------------------------------------------
__device__ void cont_dev(const float* __restrict__ att,
                         const float* __restrict__ Wc,
                         const float* __restrict__ bc,
                         float* __restrict__ out, int vb,
                         float* in_s, float* red)
{
    const int tid = threadIdx.x;
    const int cp  = tid & 31;
    const int slc = tid >> 5;
    const int col0 = vb * 64 + 2 * cp;
    const int colc = col0 <= VV - 2 ? col0 : VV - 2;

    u64 acc[2][8];
#pragma unroll
    for (int j = 0; j < 2; j++)
#pragma unroll
        for (int m = 0; m < 8; m++) acc[j][m] = 0ull;

    for (int k0 = 0; k0 < DD; k0 += 128) {
        __syncthreads();
#pragma unroll
        for (int i = 0; i < 4; i++) {
            int e = tid + 512 * i;
            int b = e >> 7, k = e & 127;
            float s = 0.f;
#pragma unroll
            for (int sc = 0; sc < 8; sc++)
                s += att[(size_t)sc * BB * DD + b * DD + k0 + k];
            in_s[k * 18 + b] = s;
        }
        __syncthreads();
#pragma unroll
        for (int kk = 0; kk < 8; kk++) {
            int k = slc * 8 + kk;
            float2 w = *(const float2*)&Wc[(size_t)(k0 + k) * VV + colc];
            u64 w0 = pk2(w.x, w.x), w1 = pk2(w.y, w.y);
            const u64* ip = (const u64*)&in_s[k * 18];
#pragma unroll
            for (int m = 0; m < 8; m++) {
                acc[0][m] = ffma2(ip[m], w0, acc[0][m]);
                acc[1][m] = ffma2(ip[m], w1, acc[1][m]);
            }
        }
    }
#pragma unroll
    for (int j = 0; j < 2; j++) {
        float* rp = &red[slc * 1024 + (2 * cp + j) * 16];
#pragma unroll
        for (int m = 0; m < 8; m++) {
            float lo, hi; upk2(acc[j][m], lo, hi);
            rp[2 * m] = lo; rp[2 * m + 1] = hi;
        }
    }
    __syncthreads();
    for (int o = tid; o < 1024; o += 512) {
        int c = o >> 4, b = o & 15;
        float s = 0.f;
#pragma unroll
        for (int sl = 0; sl < 16; sl++) s += red[sl * 1024 + c * 16 + b];
        int cg = vb * 64 + c;
        if (cg < VV)
            out[b * VV + cg] = 1.f / (1.f + expf(-(s + bc[cg])));
    }
    __syncthreads();
}

// ---------------------------------------------------------------------------
// Device fn: order-preserving compaction for batch b.
// ---------------------------------------------------------------------------
__device__ void compact_dev(const float* __restrict__ cont,
                            int* __restrict__ idx, int* __restrict__ cnt,
                            int b)
{
    const int tid = threadIdx.x;
    const int lane = tid & 31, wrp = tid >> 5;
    __shared__ int wexc[16];
    __shared__ int s_base, s_tot;
    if (tid == 0) s_base = 0;
    __syncthreads();
    for (int v0 = 0; v0 < VV; v0 += 512) {
        int v = v0 + tid;
        int m = (v < VV) && (cont[b * VV + v] > 0.5f);
        unsigned bal = __ballot_sync(0xffffffffu, m);
        int wsum = __popc(bal);
        int pw = __popc(bal & ((1u << lane) - 1u));
        if (lane == 0) wexc[wrp] = wsum;
        __syncthreads();
        if (tid < 16) {
            int sv = wexc[tid];
            int e = sv;
#pragma unroll
            for (int d = 1; d < 16; d <<= 1) {
                int t = __shfl_up_sync(0xffffu, e, d);
                if (tid >= d) e += t;
            }
            wexc[tid] = e - sv;
            if (tid == 15) s_tot = e;
        }
        __syncthreads();
        int pos = s_base + wexc[wrp] + pw;
        if (v < VV && m) idx[b * VV + pos] = v;
        __syncthreads();
        if (tid == 0) s_base += s_tot;
        __syncthreads();
    }
    if (tid == 0) cnt[b] = s_base;
}

// ---------------------------------------------------------------------------
// Device fn: one P tile (128 v x 64 h), K=256, fp16 1-term. (512 thr)
// ---------------------------------------------------------------------------
__device__ void ptile_dev(const float* __restrict__ pos,
                          const __half* __restrict__ B1h,
                          __half* __restrict__ Ph,
                          int tile, char* smem, u32 sb)
{
    const int vb = tile >> 3, hb = tile & 7;
    const int vbase = vb * 128, hbase = hb * 64;
    const int tid = threadIdx.x;
    const int wid = tid >> 5, l = tid & 31;
    const int wm = wid & 7, wn = wid >> 3;
    const int r = tid & 127, quarter = tid >> 7;
    const int v = vbase + r;
    const int vc = v < VV ? v : VV - 1;
    const float* __restrict__ prow = pos + (size_t)vc * PDIM + quarter * 16;

    float acc[4][4];
#pragma unroll
    for (int j = 0; j < 4; j++)
#pragma unroll
        for (int q = 0; q < 4; q++) acc[j][q] = 0.f;

    for (int ch = 0; ch < 4; ch++) {
        __syncthreads();
        {
            float x[16];
#pragma unroll
            for (int q = 0; q < 4; q++) {
                float4 p4 = *(const float4*)(prow + ch * 64 + 4 * q);
                x[4*q+0] = p4.x; x[4*q+1] = p4.y; x[4*q+2] = p4.z; x[4*q+3] = p4.w;
            }
            u32 hw[8];
#pragma unroll
            for (int i = 0; i < 8; i++)
                hw[i] = h2u(__floats2half2_rn(x[2*i], x[2*i+1]));
            const u32 c0 = (u32)(quarter * 2);
            const u32 q7 = (u32)r & 7u;
            const u32 off0 = (u32)(r << 7) + ((c0 ^ q7) << 4);
            const u32 off1 = (u32)(r << 7) + (((c0 + 1u) ^ q7) << 4);
            asm volatile("st.shared.v4.b32 [%0], {%1,%2,%3,%4};"
                :: "r"(sb + SMP_HH + off0), "r"(hw[0]), "r"(hw[1]), "r"(hw[2]), "r"(hw[3]) : "memory");
            asm volatile("st.shared.v4.b32 [%0], {%1,%2,%3,%4};"
                :: "r"(sb + SMP_HH + off1), "r"(hw[4]), "r"(hw[5]), "r"(hw[6]), "r"(hw[7]) : "memory");
        }
        ((uint4*)(smem + SMP_B))[tid] =
            ((const uint4*)(B1h + (size_t)ch * 32768 + (size_t)hbase * 64))[tid];
        __syncthreads();
#pragma unroll
        for (int ks = 0; ks < 4; ks++) {
            u32 ah[4];
            {
                int ra = wm * 16 + (l & 15);
                u32 chk = (((u32)(l >> 4) + 2u * ks) ^ ((u32)ra & 7u)) << 4;
                ldm_x4(ah, sb + SMP_HH + (u32)(ra << 7) + chk);
            }
#pragma unroll
            for (int p = 0; p < 2; p++) {
                int rb = wn * 32 + p * 16 + (l & 7) + ((l >> 4) & 1) * 8;
                u32 cf = 2u * ks + ((u32)(l >> 3) & 1u);
                u32 bb[4];
                ldm_x4(bb, sb + SMP_B + (u32)(rb << 7) + ((cf ^ ((u32)rb & 7u)) << 4));
#pragma unroll
                for (int t = 0; t < 2; t++)
                    mma_f16(acc[p * 2 + t], ah, &bb[2 * t]);
            }
        }
    }
    __syncthreads();

    const int g = l >> 2, tg = l & 3;
    const int i0 = vbase + wm * 16 + g;
    const int i1 = i0 + 8;
#pragma unroll
    for (int nt = 0; nt < 4; nt++) {
        const int col = hbase + wn * 32 + nt * 8 + tg * 2;
        if (i0 < VV)
            *(__half2*)&Ph[(size_t)i0 * HID + col]
                = __floats2half2_rn(acc[nt][0], acc[nt][1]);
        if (i1 < VV)
            *(__half2*)&Ph[(size_t)i1 * HID + col]
                = __floats2half2_rn(acc[nt][2], acc[nt][3]);
    }
}

__device__ __forceinline__ void ptile1(const float* pos, const __half* B1h,
                                       __half* Ph, int t, char* smem, u32 sb)
{
    if (t >= 0 && t < NPTILE) ptile_dev(pos, B1h, Ph, t, smem, sb);
}

// ---------------------------------------------------------------------------
// MEGA front-end (R15): s1(+prep) | s2 | s3 | s4 | s5 | P tail.
// ---------------------------------------------------------------------------
__global__ void __launch_bounds__(512, 1)
k_front(const float* __restrict__ features,
        const float* __restrict__ W_contact, const float* __restrict__ b_contact,
        const float* __restrict__ Wv, const float* __restrict__ Wo,
        const float* __restrict__ W_cls, const float* __restrict__ b_cls,
        const float* __restrict__ W_ft1, const float* __restrict__ b_ft1,
        const float* __restrict__ W_ft2, const float* __restrict__ pos,
        float* __restrict__ part, float* __restrict__ tmp,
        float* __restrict__ att, float* __restrict__ a,
        float* __restrict__ cont, int* __restrict__ idx, int* __restrict__ cnt,
        __half* __restrict__ Bimg, __half* __restrict__ B1h,
        __half* __restrict__ Ph)
{
    extern __shared__ char smemc[];
    float* in_s = (float*)smemc;
    float* red  = (float*)(smemc + 192 * 18 * 4);
    const u32 sb = smem_u32(smemc);
    const int bid = blockIdx.x;
    const int tid = threadIdx.x;

    if (bid < 128) {
        skinny64_dev(features, W_contact, b_contact, part, DF, DD, 1,
                     bid & 15, bid >> 4, 192, in_s, red);
    } else if (bid < 136) {
        const int img = bid - 128;
        for (int e = tid; e < BROWS * 64; e += 512) {
            int n = e >> 6, k = e & 63;
            float w = (n < CC) ? W_ft2[(size_t)(img * 64 + k) * CC + n] : 0.f;
            int off = (n << 6) + (((k >> 3) ^ (n & 7)) << 3) + (k & 7);
            Bimg[(size_t)img * (BROWS * 64) + off] = __float2half_rn(w);
        }
    } else if (bid < 140) {
        const int ch = bid - 136;
        for (int e = tid; e < 512 * 64; e += 512) {
            int n = e >> 6, k = e & 63;
            float w = W_ft1[(size_t)(DD + ch * 64 + k) * HID + n];
            int off = (n << 6) + (((k >> 3) ^ (n & 7)) << 3) + (k & 7);
            B1h[(size_t)ch * (512 * 64) + off] = __float2half_rn(w);
        }
    }
    grid_bar(NPERS);
    if (bid < 128)
        skinny64_dev(part, Wv, nullptr, tmp, DD, DD, 8, bid & 15, bid >> 4,
                     128, in_s, red);
    else
        ptile1(pos, B1h, Ph, bid - 128, smemc, sb);
    grid_bar(NPERS);
    if (bid < 128)
        skinny64_dev(tmp, Wo, nullptr, att, DD, DD, 8, bid & 15, bid >> 4,
                     128, in_s, red);
    else
        ptile1(pos, B1h, Ph, 20 + bid - 128, smemc, sb);
    grid_bar(NPERS);
    if (bid < 108)
        cont_dev(att, W_cls, b_cls, cont, bid, in_s, red);
    else
        ptile1(pos, B1h, Ph, 40 + bid - 108, smemc, sb);
    grid_bar(NPERS);
    if (bid < 64)
        skinny64_dev(att, W_ft1, b_ft1, a, DD, HID, 8, bid & 7, bid >> 3,
                     128, in_s, red);
    else if (bid < 80)
        compact_dev(cont, idx, cnt, bid - 64);
    else
        ptile1(pos, B1h, Ph, 80 + bid - 80, smemc, sb);
    ptile1(pos, B1h, Ph, 148 + bid, smemc, sb);
    ptile1(pos, B1h, Ph, 296 + bid, smemc, sb);
}

// ---------------------------------------------------------------------------
// PERSISTENT main GEMM: 64-row tiles, 256 thr (8 warps = 4m x 2n), 2 CTAs/SM
// (grid=296). B chunks double-buffered via cp.async. P fp16. Fused scattered
// epilogue; prologue zeroes sem + grid barrier (296).
// ---------------------------------------------------------------------------
__global__ void __launch_bounds__(256, 2)
k_sem_mma(const float* __restrict__ A8,
          const __half* __restrict__ Ph,
          const __half* __restrict__ Bimg,
          const float* __restrict__ b2,
          const int* __restrict__ idx,
          const int* __restrict__ cnt,
          float* __restrict__ sem)
{
    extern __shared__ char smem[];
    const u32 sb = smem_u32(smem);
    const int tid = threadIdx.x;
    const int wid = tid >> 5;
    const int l   = tid & 31;
    const int wm = wid & 3;          // m16 tile (rows wm*16..+16 of 64)
    const int wn = wid >> 2;         // 0/1: cols wn*72..+72
    const int r = tid & 63;          // producer row
    const int seg = tid >> 6;        // producer k-segment (16 k of 64)
    const u32 qr = ((u32)r >> 3) & 3;
    const u32 hrow_off = (u32)(r * 144);

    // zero sem across all 296 CTAs, then barrier
    {
        float4* z = (float4*)sem;
        const int n4 = (BB * CC * VV) / 4;
        for (int i = blockIdx.x * 256 + tid; i < n4; i += NSEM * 256)
            z[i] = make_float4(0.f, 0.f, 0.f, 0.f);
    }
    grid_bar(NSEM);

    int offv[17];
    offv[0] = 0;
#pragma unroll
    for (int b = 0; b < 16; b++)
        offv[b + 1] = offv[b] + ((cnt[b] + 63) >> 6);
    const int total = offv[16];

    float* a_sm = (float*)(smem + S2_AS);

    for (int w = blockIdx.x; w < total; w += NSEM) {
        int b = 0;
#pragma unroll
        for (int t = 0; t < 15; t++) if (w >= offv[b + 1]) b++;
        const int cntb = cnt[b];
        const int ibase = (w - offv[b]) << 6;

        // stage a[b] (sum of 8 partials), 2 elems/thread
#pragma unroll
        for (int ii = 0; ii < 2; ii++) {
            int i = tid + 256 * ii;
            float s = 0.f;
#pragma unroll
            for (int sc = 0; sc < 8; sc++)
                s += A8[(size_t)sc * BB * HID + b * HID + i];
            a_sm[i] = s;
        }

        const int ig = ibase + r;
        const int vrow = idx[b * VV + (ig < cntb ? ig : cntb - 1)];
        const __half* __restrict__ prow = Ph + (size_t)vrow * HID + seg * 16;

        float acc[9][4];
#pragma unroll
        for (int j = 0; j < 9; j++)
#pragma unroll
            for (int q = 0; q < 4; q++) acc[j][q] = 0.f;

        // B(0) cp.async + P(0) prefetch
        {
            const char* srcB = (const char*)(Bimg);
            u32 dstB = sb + S2_B(0);
            for (int e = tid; e < 1088; e += 256)
                cpasync16(dstB + e * 16, srcB + e * 16);
            cpasync_commit();
        }
        uint4 pf[2];
        pf[0] = *(const uint4*)(prow);
        pf[1] = *(const uint4*)(prow + 8);
        __syncthreads();   // a_sm ready; previous tile's MMAs done

        // produce H(0)
        {
            const float* ap = a_sm + seg * 16;
            const __half2* ph = (const __half2*)pf;
            u32 hw[8];
#pragma unroll
            for (int i = 0; i < 8; i++) {
                float2 p2 = __half22float2(ph[i]);
                float x0 = fmaxf(p2.x + ap[2*i],     0.f);
                float x1 = fmaxf(p2.y + ap[2*i + 1], 0.f);
                hw[i] = h2u(__floats2half2_rn(x0, x1));
            }
            const u32 c0 = (u32)(seg * 2);
            const u32 off0 = hrow_off + ((c0 ^ qr) << 4);
            const u32 off1 = hrow_off + (((c0 + 1u) ^ qr) << 4);
            asm volatile("st.shared.v4.b32 [%0], {%1,%2,%3,%4};"
                :: "r"(sb + S2_H(0) + off0), "r"(hw[0]), "r"(hw[1]), "r"(hw[2]), "r"(hw[3]) : "memory");
            asm volatile("st.shared.v4.b32 [%0], {%1,%2,%3,%4};"
                :: "r"(sb + S2_H(0) + off1), "r"(hw[4]), "r"(hw[5]), "r"(hw[6]), "r"(hw[7]) : "memory");
        }
        cpasync_wait0();

        int buf = 0;
        for (int ch = 0; ch < 8; ch++) {
            __syncthreads();   // H(ch), B(ch) visible
            const int nb = buf ^ 1;
            if (ch < 7) {
                const char* srcB = (const char*)(Bimg + (size_t)(ch + 1) * (BROWS * 64));
                u32 dstB = sb + S2_B(nb);
                for (int e = tid; e < 1088; e += 256)
                    cpasync16(dstB + e * 16, srcB + e * 16);
                cpasync_commit();
                const __half* ps = prow + (ch + 1) * 64;
                pf[0] = *(const uint4*)(ps);
                pf[1] = *(const uint4*)(ps + 8);
            }

            const u32 hH = sb + S2_H(buf);
            const u32 bB = sb + S2_B(buf);
#pragma unroll
            for (int ks = 0; ks < 4; ks++) {
                u32 ah[4];
                {
                    int ra = wm * 16 + (l & 15);
                    u32 qa = ((u32)ra >> 3) & 3;
                    u32 chk = (((u32)(l >> 4) + 2u * ks) ^ qa) << 4;
                    ldm_x4(ah, hH + (u32)(ra * 144) + chk);
                }
#pragma unroll
                for (int p = 0; p < 4; p++) {
                    int rb = wn * 72 + p * 16 + (l & 7) + ((l >> 4) & 1) * 8;
                    u32 chunkf = 2u * ks + ((u32)(l >> 3) & 1u);
                    u32 bb[4];
                    ldm_x4(bb, bB + (u32)(rb << 7) + ((chunkf ^ ((u32)rb & 7u)) << 4));
#pragma unroll
                    for (int t = 0; t < 2; t++)
                        mma_f16(acc[p * 2 + t], ah, &bb[2 * t]);
                }
                {
                    int rb2 = 64 + (l & 7);
                    u32 chunkf = 2u * ks + ((u32)(l >> 3) & 1u);
                    u32 s2[2];
                    ldm_x2(s2, bB + (u32)(rb2 << 7) + ((chunkf ^ ((u32)rb2 & 7u)) << 4));
                    mma_f16(acc[8], ah, s2);
                }
            }

            if (ch < 7) {
                const float* ap = a_sm + (ch + 1) * 64 + seg * 16;
                const __half2* ph = (const __half2*)pf;
                u32 hw[8];
#pragma unroll
                for (int i = 0; i < 8; i++) {
                    float2 p2 = __half22float2(ph[i]);
                    float x0 = fmaxf(p2.x + ap[2*i],     0.f);
                    float x1 = fmaxf(p2.y + ap[2*i + 1], 0.f);
                    hw[i] = h2u(__floats2half2_rn(x0, x1));
                }
                const u32 c0 = (u32)(seg * 2);
                const u32 off0 = hrow_off + ((c0 ^ qr) << 4);
                const u32 off1 = hrow_off + (((c0 + 1u) ^ qr) << 4);
                asm volatile("st.shared.v4.b32 [%0], {%1,%2,%3,%4};"
                    :: "r"(sb + S2_H(nb) + off0), "r"(hw[0]), "r"(hw[1]), "r"(hw[2]), "r"(hw[3]) : "memory");
                asm volatile("st.shared.v4.b32 [%0], {%1,%2,%3,%4};"
                    :: "r"(sb + S2_H(nb) + off1), "r"(hw[4]), "r"(hw[5]), "r"(hw[6]), "r"(hw[7]) : "memory");
                cpasync_wait0();
            }
            buf = nb;
        }

        // fused epilogue: bias + scattered store sem[b, col, idx[i]]
        const int g = l >> 2, tg = l & 3;
        const int i0 = ibase + wm * 16 + g;
        const int i1 = i0 + 8;
        const bool ok0 = i0 < cntb, ok1 = i1 < cntb;
        const int v0 = ok0 ? idx[b * VV + i0] : 0;
        const int v1 = ok1 ? idx[b * VV + i1] : 0;
#pragma unroll
        for (int nt = 0; nt < 9; nt++) {
            const int cbase = wn * 72 + nt * 8 + tg * 2;
#pragma unroll
            for (int q = 0; q < 2; q++) {
                const int col = cbase + q;
                if (col >= CC) continue;
                const float bias = __ldg(&b2[col]);
                if (ok0) sem[((size_t)b * CC + col) * VV + v0] = acc[nt][q] + bias;
                if (ok1) sem[((size_t)b * CC + col) * VV + v1] = acc[nt][2 + q] + bias;
            }
        }
    }
}

// ---------------------------------------------------------------------------
extern "C" void kernel_launch(void* const* d_in, const int* in_sizes, int n_in,
                              void* d_out, int out_size)
{
    const float* features  = (const float*)d_in[0];
    const float* W_contact = (const float*)d_in[3];
    const float* b_contact = (const float*)d_in[4];
    const float* Wv        = (const float*)d_in[7];
    const float* Wo        = (const float*)d_in[8];
    const float* W_cls     = (const float*)d_in[9];
    const float* b_cls     = (const float*)d_in[10];
    const float* pos_emb   = (const float*)d_in[11];
    const float* W_ft1     = (const float*)d_in[12];
    const float* b_ft1     = (const float*)d_in[13];
    const float* W_ft2     = (const float*)d_in[14];
    const float* b_ft2     = (const float*)d_in[15];

    float* out  = (float*)d_out;
    float* cont = out;                  // [16, 6890]
    float* sem  = out + BB * VV;        // [16, 133, 6890]

    float *part, *tmp, *att, *a;
    __half *Ph, *Bimg, *B1h;
    int *idx, *cnt;
    cudaGetSymbolAddress((void**)&part,  g_part);
    cudaGetSymbolAddress((void**)&tmp,   g_tmp);
    cudaGetSymbolAddress((void**)&att,   g_att);
    cudaGetSymbolAddress((void**)&a,     g_a);
    cudaGetSymbolAddress((void**)&Ph,    g_Ph);
    cudaGetSymbolAddress((void**)&idx,   g_idx);
    cudaGetSymbolAddress((void**)&cnt,   g_cnt);
    cudaGetSymbolAddress((void**)&Bimg,  g_Bimg);
    cudaGetSymbolAddress((void**)&B1h,   g_B1h);

    cudaFuncSetAttribute(k_sem_mma, cudaFuncAttributeMaxDynamicSharedMemorySize, S2_TOT);
    cudaFuncSetAttribute(k_front,   cudaFuncAttributeMaxDynamicSharedMemorySize, SMF_TOT);

    // front-end: prep + chain + P overlapped/tail
    k_front<<<NPERS, 512, SMF_TOT>>>(features, W_contact, b_contact, Wv, Wo,
                                     W_cls, b_cls, W_ft1, b_ft1, W_ft2,
                                     pos_emb, part, tmp, att, a, cont,
                                     idx, cnt, Bimg, B1h, Ph);

    // main GEMM: 64-row tiles, 2 CTAs/SM
    k_sem_mma<<<NSEM, 256, S2_TOT>>>(a, Ph, Bimg, b_ft2, idx, cnt, sem);
}

// round 17
// speedup vs baseline: 1.2304x; 1.0269x over previous
#include <cuda_runtime.h>
#include <cuda_fp16.h>
#include <cuda_bf16.h>
#include <math.h>

// DECO decomposed (len-1 softmax == 1 → Wq/Wk/W_scene dead):
//   att  = (feat @ W_contact + b_c) @ Wv @ Wo            [16,1024]
//   cont = sigmoid(att @ W_cls + b_cls)                  [16,6890]
//   a    = att @ W_ft1[:1024] + b_ft1                    [16,512]
//   P    = pos_emb @ W_ft1[1024:]   (HMMA fp16 1-term, stored fp16)
//   sem[b,c,v] = mask * (relu(a[b]+P[v]) @ W_ft2 + b2)[c]
// R17: P tile single-staged (full K=256 H + all 4 B images in smem, one sync
// pair, 16 straight MMA steps) -> P no longer dominates the chain barriers.
// k_sem unchanged (R16: 64-row tiles, 2 CTAs/SM, grid 296).

#define BB   16
#define DF   1536
#define DD   1024
#define VV   6890
#define PDIM 256
#define HID  512
#define CC   133
#define NC   144
#define BROWS 136
#define NPERS 148
#define NSEM  296
#define NPTILE 432

typedef unsigned long long u64;
typedef unsigned int u32;

__device__ float g_part[8 * BB * DD];
__device__ float g_tmp [8 * BB * DD];
__device__ float g_att [8 * BB * DD];
__device__ float g_a   [8 * BB * HID];
__device__ __align__(16) __half g_Ph[VV * HID];
__device__ int   g_idx [BB * VV];
__device__ int   g_cnt [BB];
__device__ __align__(16) __half g_Bimg[8 * BROWS * 64];
__device__ __align__(16) __half g_B1h[4 * 512 * 64];
__device__ int   g_bar_arrive;
__device__ unsigned int g_bar_gen;

__device__ __forceinline__ u64 pk2(float lo, float hi) {
    u64 r; asm("mov.b64 %0, {%1, %2};" : "=l"(r) : "f"(lo), "f"(hi)); return r;
}
__device__ __forceinline__ void upk2(u64 v, float& lo, float& hi) {
    asm("mov.b64 {%0, %1}, %2;" : "=f"(lo), "=f"(hi) : "l"(v));
}
__device__ __forceinline__ u64 ffma2(u64 a, u64 b, u64 c) {
    u64 d; asm("fma.rn.f32x2 %0, %1, %2, %3;" : "=l"(d) : "l"(a), "l"(b), "l"(c));
    return d;
}
__device__ __forceinline__ u32 smem_u32(const void* p) {
    u32 a; asm("{ .reg .u64 t; cvta.to.shared.u64 t, %1; cvt.u32.u64 %0, t; }"
               : "=r"(a) : "l"(p));
    return a;
}
__device__ __forceinline__ void ldm_x4(u32* r, u32 addr) {
    asm volatile("ldmatrix.sync.aligned.m8n8.x4.shared.b16 {%0,%1,%2,%3}, [%4];"
        : "=r"(r[0]), "=r"(r[1]), "=r"(r[2]), "=r"(r[3]) : "r"(addr));
}
__device__ __forceinline__ void ldm_x2(u32* r, u32 addr) {
    asm volatile("ldmatrix.sync.aligned.m8n8.x2.shared.b16 {%0,%1}, [%2];"
        : "=r"(r[0]), "=r"(r[1]) : "r"(addr));
}
__device__ __forceinline__ void mma_f16(float* d, const u32* a, const u32* b) {
    asm volatile("mma.sync.aligned.m16n8k16.row.col.f32.f16.f16.f32 "
        "{%0,%1,%2,%3}, {%4,%5,%6,%7}, {%8,%9}, {%0,%1,%2,%3};"
        : "+f"(d[0]), "+f"(d[1]), "+f"(d[2]), "+f"(d[3])
        : "r"(a[0]), "r"(a[1]), "r"(a[2]), "r"(a[3]), "r"(b[0]), "r"(b[1]));
}
__device__ __forceinline__ u32 h2u(__half2 h) {
    u32 r; asm("mov.b32 %0, %1;" : "=r"(r) : "r"(*(u32*)&h)); return r;
}
__device__ __forceinline__ void cpasync16(u32 dst, const void* src) {
    asm volatile("cp.async.cg.shared.global [%0], [%1], 16;"
                 :: "r"(dst), "l"(src) : "memory");
}
__device__ __forceinline__ void cpasync_commit() {
    asm volatile("cp.async.commit_group;" ::: "memory");
}
__device__ __forceinline__ void cpasync_wait0() {
    asm volatile("cp.async.wait_group 0;" ::: "memory");
}

__device__ __forceinline__ void grid_bar(int nctas) {
    __syncthreads();
    if (threadIdx.x == 0) {
        __threadfence();
        unsigned gen = atomicAdd(&g_bar_gen, 0u);
        int a = atomicAdd(&g_bar_arrive, 1);
        if (a == nctas - 1) {
            g_bar_arrive = 0;
            __threadfence();
            atomicAdd(&g_bar_gen, 1u);
        } else {
            while (atomicAdd(&g_bar_gen, 0u) == gen) {}
        }
        __threadfence();
    }
    __syncthreads();
}

// k_sem smem layout (bytes), 256 thr, 64-row tiles
#define S2_AS    0
#define S2_H(bf) (2048 + (bf) * 9216)
#define S2_B(bf) (20480 + (bf) * 17408)
#define S2_TOT   55296
// k_front smem views: chain (in_s 13824 + red 65536), ptile (H 64KB | B 32KB)
#define SMF_TOT  122880
#define SMP_HH 0
#define SMP_B  65536

// ---------------------------------------------------------------------------
// Device fn: single-iteration split-K skinny GEMM vblock (512 thr).
// ---------------------------------------------------------------------------
__device__ void skinny64_dev(const float* __restrict__ in,
                             const float* __restrict__ W,
                             const float* __restrict__ bias,
                             float* __restrict__ out,
                             int K, int N, int nsum, int colb, int ky,
                             int kspan, float* in_s, float* red)
{
    const int tid = threadIdx.x;
    const int col = tid & 63;
    const int slc = tid >> 6;
    const int colg = colb * 64 + col;
    const int kbase = ky * kspan;
    const int kper = kspan >> 3;

    for (int e = tid; e < kspan * 16; e += 512) {
        int b = e / kspan;
        int k = e - b * kspan;
        float s = 0.f;
        for (int sc = 0; sc < nsum; sc++)
            s += in[(size_t)sc * BB * K + b * K + kbase + k];
        in_s[k * 18 + b] = s;
    }
    __syncthreads();

    u64 acc2[8];
#pragma unroll
    for (int m = 0; m < 8; m++) acc2[m] = 0ull;

    for (int kk = 0; kk < kper; kk++) {
        int k = slc * kper + kk;
        float w = W[(size_t)(kbase + k) * N + colg];
        u64 w2 = pk2(w, w);
        const u64* ip = (const u64*)&in_s[k * 18];
#pragma unroll
        for (int m = 0; m < 8; m++)
            acc2[m] = ffma2(ip[m], w2, acc2[m]);
    }
    float* rp = &red[slc * 1088 + col * 17];
#pragma unroll
    for (int m = 0; m < 8; m++) {
        float lo, hi; upk2(acc2[m], lo, hi);
        rp[2 * m] = lo; rp[2 * m + 1] = hi;
    }
    __syncthreads();
    for (int o = tid; o < 1024; o += 512) {
        int c = o >> 4, b = o & 15;
        float s = 0.f;
#pragma unroll
        for (int sl = 0; sl < 8; sl++) s += red[sl * 1088 + c * 17 + b];
        float bb = (bias && ky == 0) ? bias[colb * 64 + c] : 0.f;
        out[(size_t)ky * BB * N + b * N + colb * 64 + c] = s + bb;
    }
    __syncthreads();
}

// ---------------------------------------------------------------------------
// Device fn: cont vblock (64 cols), sums 8 att partials.
// ---------------------------------------------------------------------------
__device__ void cont_dev(const float* __restrict__ att,
                         const float* __restrict__ Wc,
                         const float* __restrict__ bc,
                         float* __restrict__ out, int vb,
                         float* in_s, float* red)
{
    const int tid = threadIdx.x;
    const int cp  = tid & 31;
    const int slc = tid >> 5;
    const int col0 = vb * 64 + 2 * cp;
    const int colc = col0 <= VV - 2 ? col0 : VV - 2;

    u64 acc[2][8];
#pragma unroll
    for (int j = 0; j < 2; j++)
#pragma unroll
        for (int m = 0; m < 8; m++) acc[j][m] = 0ull;

    for (int k0 = 0; k0 < DD; k0 += 128) {
        __syncthreads();
#pragma unroll
        for (int i = 0; i < 4; i++) {
            int e = tid + 512 * i;
            int b = e >> 7, k = e & 127;
            float s = 0.f;
#pragma unroll
            for (int sc = 0; sc < 8; sc++)
                s += att[(size_t)sc * BB * DD + b * DD + k0 + k];
            in_s[k * 18 + b] = s;
        }
        __syncthreads();
#pragma unroll
        for (int kk = 0; kk < 8; kk++) {
            int k = slc * 8 + kk;
            float2 w = *(const float2*)&Wc[(size_t)(k0 + k) * VV + colc];
            u64 w0 = pk2(w.x, w.x), w1 = pk2(w.y, w.y);
            const u64* ip = (const u64*)&in_s[k * 18];
#pragma unroll
            for (int m = 0; m < 8; m++) {
                acc[0][m] = ffma2(ip[m], w0, acc[0][m]);
                acc[1][m] = ffma2(ip[m], w1, acc[1][m]);
            }
        }
    }
#pragma unroll
    for (int j = 0; j < 2; j++) {
        float* rp = &red[slc * 1024 + (2 * cp + j) * 16];
#pragma unroll
        for (int m = 0; m < 8; m++) {
            float lo, hi; upk2(acc[j][m], lo, hi);
            rp[2 * m] = lo; rp[2 * m + 1] = hi;
        }
    }
    __syncthreads();
    for (int o = tid; o < 1024; o += 512) {
        int c = o >> 4, b = o & 15;
        float s = 0.f;
#pragma unroll
        for (int sl = 0; sl < 16; sl++) s += red[sl * 1024 + c * 16 + b];
        int cg = vb * 64 + c;
        if (cg < VV)
            out[b * VV + cg] = 1.f / (1.f + expf(-(s + bc[cg])));
    }
    __syncthreads();
}

// ---------------------------------------------------------------------------
// Device fn: order-preserving compaction for batch b.
// ---------------------------------------------------------------------------
__device__ void compact_dev(const float* __restrict__ cont,
                            int* __restrict__ idx, int* __restrict__ cnt,
                            int b)
{
    const int tid = threadIdx.x;
    const int lane = tid & 31, wrp = tid >> 5;
    __shared__ int wexc[16];
    __shared__ int s_base, s_tot;
    if (tid == 0) s_base = 0;
    __syncthreads();
    for (int v0 = 0; v0 < VV; v0 += 512) {
        int v = v0 + tid;
        int m = (v < VV) && (cont[b * VV + v] > 0.5f);
        unsigned bal = __ballot_sync(0xffffffffu, m);
        int wsum = __popc(bal);
        int pw = __popc(bal & ((1u << lane) - 1u));
        if (lane == 0) wexc[wrp] = wsum;
        __syncthreads();
        if (tid < 16) {
            int sv = wexc[tid];
            int e = sv;
#pragma unroll
            for (int d = 1; d < 16; d <<= 1) {
                int t = __shfl_up_sync(0xffffu, e, d);
                if (tid >= d) e += t;
            }
            wexc[tid] = e - sv;
            if (tid == 15) s_tot = e;
        }
        __syncthreads();
        int pos = s_base + wexc[wrp] + pw;
        if (v < VV && m) idx[b * VV + pos] = v;
        __syncthreads();
        if (tid == 0) s_base += s_tot;
        __syncthreads();
    }
    if (tid == 0) cnt[b] = s_base;
}

// ---------------------------------------------------------------------------
// Device fn: one P tile (128 v x 64 h), K=256, fp16 1-term, SINGLE-STAGED:
// full H (128x256 fp16, 64KB) + all 4 B chunk images (32KB) in smem, one
// sync pair, then 16 straight k16 MMA steps. 512 thr = 8m x 2n warps.
// H layout: row stride 512B, 16B chunk ck swizzled ck^(r&7).
// ---------------------------------------------------------------------------
__device__ void ptile_dev(const float* __restrict__ pos,
                          const __half* __restrict__ B1h,
                          __half* __restrict__ Ph,
                          int tile, char* smem, u32 sb)
{
    const int vb = tile >> 3, hb = tile & 7;
    const int vbase = vb * 128, hbase = hb * 64;
    const int tid = threadIdx.x;
    const int wid = tid >> 5, l = tid & 31;
    const int wm = wid & 7, wn = wid >> 3;
    const int r = tid & 127;           // row
    const int seg = tid >> 7;          // k-segment (64 k each, 4 segs)
    const int v = vbase + r;
    const int vc = v < VV ? v : VV - 1;
    const float* __restrict__ prow = pos + (size_t)vc * PDIM + seg * 64;

    __syncthreads();   // guard smem reuse from caller's previous phase

    // producer: 64 pos floats -> fp16, 8 swizzled 16B chunks
    {
        const u32 r7 = (u32)r & 7u;
        const u32 rowoff = (u32)(r << 9);
#pragma unroll
        for (int c8 = 0; c8 < 8; c8++) {
            float4 a0 = *(const float4*)(prow + c8 * 8);
            float4 a1 = *(const float4*)(prow + c8 * 8 + 4);
            u32 h0 = h2u(__floats2half2_rn(a0.x, a0.y));
            u32 h1 = h2u(__floats2half2_rn(a0.z, a0.w));
            u32 h2 = h2u(__floats2half2_rn(a1.x, a1.y));
            u32 h3 = h2u(__floats2half2_rn(a1.z, a1.w));
            u32 ck = (u32)(seg * 8 + c8);
            u32 off = rowoff + ((ck ^ r7) << 4);
            asm volatile("st.shared.v4.b32 [%0], {%1,%2,%3,%4};"
                :: "r"(sb + SMP_HH + off), "r"(h0), "r"(h1), "r"(h2), "r"(h3)
                : "memory");
        }
    }
    // B: all 4 chunk images (64 rows x 128B each = 512 uint4 per image)
#pragma unroll
    for (int ch = 0; ch < 4; ch++)
        ((uint4*)(smem + SMP_B + ch * 8192))[tid] =
            ((const uint4*)(B1h + (size_t)ch * 32768 + (size_t)hbase * 64))[tid];
    __syncthreads();

    float acc[4][4];
#pragma unroll
    for (int j = 0; j < 4; j++)
#pragma unroll
        for (int q = 0; q < 4; q++) acc[j][q] = 0.f;

#pragma unroll
    for (int ks = 0; ks < 16; ks++) {
        u32 ah[4];
        {
            int ra = wm * 16 + (l & 15);
            u32 ck = (u32)(l >> 4) + 2u * (u32)ks;
            ldm_x4(ah, sb + SMP_HH + (u32)(ra << 9) + ((ck ^ ((u32)ra & 7u)) << 4));
        }
        const u32 img = (u32)(ks >> 2);
        const u32 cf = 2u * (u32)(ks & 3) + ((u32)(l >> 3) & 1u);
#pragma unroll
        for (int p = 0; p < 2; p++) {
            int rb = wn * 32 + p * 16 + (l & 7) + ((l >> 4) & 1) * 8;
            u32 bb[4];
            ldm_x4(bb, sb + SMP_B + (img << 13) + (u32)(rb << 7)
                        + ((cf ^ ((u32)rb & 7u)) << 4));
#pragma unroll
            for (int t = 0; t < 2; t++)
                mma_f16(acc[p * 2 + t], ah, &bb[2 * t]);
        }
    }
    __syncthreads();   // all ldmatrix done before smem reuse

    const int g = l >> 2, tg = l & 3;
    const int i0 = vbase + wm * 16 + g;
    const int i1 = i0 + 8;
#pragma unroll
    for (int nt = 0; nt < 4; nt++) {
        const int col = hbase + wn * 32 + nt * 8 + tg * 2;
        if (i0 < VV)
            *(__half2*)&Ph[(size_t)i0 * HID + col]
                = __floats2half2_rn(acc[nt][0], acc[nt][1]);
        if (i1 < VV)
            *(__half2*)&Ph[(size_t)i1 * HID + col]
                = __floats2half2_rn(acc[nt][2], acc[nt][3]);
    }
}

__device__ __forceinline__ void ptile1(const float* pos, const __half* B1h,
                                       __half* Ph, int t, char* smem, u32 sb)
{
    if (t >= 0 && t < NPTILE) ptile_dev(pos, B1h, Ph, t, smem, sb);
}

// ---------------------------------------------------------------------------
// MEGA front-end: s1(+prep) | s2 | s3 | s4 | s5 | P tail. 4 grid barriers.
// ---------------------------------------------------------------------------
__global__ void __launch_bounds__(512, 1)
k_front(const float* __restrict__ features,
        const float* __restrict__ W_contact, const float* __restrict__ b_contact,
        const float* __restrict__ Wv, const float* __restrict__ Wo,
        const float* __restrict__ W_cls, const float* __restrict__ b_cls,
        const float* __restrict__ W_ft1, const float* __restrict__ b_ft1,
        const float* __restrict__ W_ft2, const float* __restrict__ pos,
        float* __restrict__ part, float* __restrict__ tmp,
        float* __restrict__ att, float* __restrict__ a,
        float* __restrict__ cont, int* __restrict__ idx, int* __restrict__ cnt,
        __half* __restrict__ Bimg, __half* __restrict__ B1h,
        __half* __restrict__ Ph)
{
    extern __shared__ char smemc[];
    float* in_s = (float*)smemc;
    float* red  = (float*)(smemc + 192 * 18 * 4);
    const u32 sb = smem_u32(smemc);
    const int bid = blockIdx.x;
    const int tid = threadIdx.x;

    if (bid < 128) {
        skinny64_dev(features, W_contact, b_contact, part, DF, DD, 1,
                     bid & 15, bid >> 4, 192, in_s, red);
    } else if (bid < 136) {
        const int img = bid - 128;
        for (int e = tid; e < BROWS * 64; e += 512) {
            int n = e >> 6, k = e & 63;
            float w = (n < CC) ? W_ft2[(size_t)(img * 64 + k) * CC + n] : 0.f;
            int off = (n << 6) + (((k >> 3) ^ (n & 7)) << 3) + (k & 7);
            Bimg[(size_t)img * (BROWS * 64) + off] = __float2half_rn(w);
        }
    } else if (bid < 140) {
        const int ch = bid - 136;
        for (int e = tid; e < 512 * 64; e += 512) {
            int n = e >> 6, k = e & 63;
            float w = W_ft1[(size_t)(DD + ch * 64 + k) * HID + n];
            int off = (n << 6) + (((k >> 3) ^ (n & 7)) << 3) + (k & 7);
            B1h[(size_t)ch * (512 * 64) + off] = __float2half_rn(w);
        }
    }
    grid_bar(NPERS);
    if (bid < 128)
        skinny64_dev(part, Wv, nullptr, tmp, DD, DD, 8, bid & 15, bid >> 4,
                     128, in_s, red);
    else
        ptile1(pos, B1h, Ph, bid - 128, smemc, sb);
    grid_bar(NPERS);
    if (bid < 128)
        skinny64_dev(tmp, Wo, nullptr, att, DD, DD, 8, bid & 15, bid >> 4,
                     128, in_s, red);
    else
        ptile1(pos, B1h, Ph, 20 + bid - 128, smemc, sb);
    grid_bar(NPERS);
    if (bid < 108)
        cont_dev(att, W_cls, b_cls, cont, bid, in_s, red);
    else
        ptile1(pos, B1h, Ph, 40 + bid - 108, smemc, sb);
    grid_bar(NPERS);
    if (bid < 64)
        skinny64_dev(att, W_ft1, b_ft1, a, DD, HID, 8, bid & 7, bid >> 3,
                     128, in_s, red);
    else if (bid < 80)
        compact_dev(cont, idx, cnt, bid - 64);
    else
        ptile1(pos, B1h, Ph, 80 + bid - 80, smemc, sb);
    ptile1(pos, B1h, Ph, 148 + bid, smemc, sb);
    ptile1(pos, B1h, Ph, 296 + bid, smemc, sb);
}

// ---------------------------------------------------------------------------
// PERSISTENT main GEMM (R16, unchanged): 64-row tiles, 256 thr, 2 CTAs/SM,
// B double-buffered cp.async, P fp16, fused scattered epilogue.
// ---------------------------------------------------------------------------
__global__ void __launch_bounds__(256, 2)
k_sem_mma(const float* __restrict__ A8,
          const __half* __restrict__ Ph,
          const __half* __restrict__ Bimg,
          const float* __restrict__ b2,
          const int* __restrict__ idx,
          const int* __restrict__ cnt,
          float* __restrict__ sem)
{
    extern __shared__ char smem[];
    const u32 sb = smem_u32(smem);
    const int tid = threadIdx.x;
    const int wid = tid >> 5;
    const int l   = tid & 31;
    const int wm = wid & 3;
    const int wn = wid >> 2;
    const int r = tid & 63;
    const int seg = tid >> 6;
    const u32 qr = ((u32)r >> 3) & 3;
    const u32 hrow_off = (u32)(r * 144);

    {
        float4* z = (float4*)sem;
        const int n4 = (BB * CC * VV) / 4;
        for (int i = blockIdx.x * 256 + tid; i < n4; i += NSEM * 256)
            z[i] = make_float4(0.f, 0.f, 0.f, 0.f);
    }
    grid_bar(NSEM);

    int offv[17];
    offv[0] = 0;
#pragma unroll
    for (int b = 0; b < 16; b++)
        offv[b + 1] = offv[b] + ((cnt[b] + 63) >> 6);
    const int total = offv[16];

    float* a_sm = (float*)(smem + S2_AS);

    for (int w = blockIdx.x; w < total; w += NSEM) {
        int b = 0;
#pragma unroll
        for (int t = 0; t < 15; t++) if (w >= offv[b + 1]) b++;
        const int cntb = cnt[b];
        const int ibase = (w - offv[b]) << 6;

#pragma unroll
        for (int ii = 0; ii < 2; ii++) {
            int i = tid + 256 * ii;
            float s = 0.f;
#pragma unroll
            for (int sc = 0; sc < 8; sc++)
                s += A8[(size_t)sc * BB * HID + b * HID + i];
            a_sm[i] = s;
        }

        const int ig = ibase + r;
        const int vrow = idx[b * VV + (ig < cntb ? ig : cntb - 1)];
        const __half* __restrict__ prow = Ph + (size_t)vrow * HID + seg * 16;

        float acc[9][4];
#pragma unroll
        for (int j = 0; j < 9; j++)
#pragma unroll
            for (int q = 0; q < 4; q++) acc[j][q] = 0.f;

        {
            const char* srcB = (const char*)(Bimg);
            u32 dstB = sb + S2_B(0);
            for (int e = tid; e < 1088; e += 256)
                cpasync16(dstB + e * 16, srcB + e * 16);
            cpasync_commit();
        }
        uint4 pf[2];
        pf[0] = *(const uint4*)(prow);
        pf[1] = *(const uint4*)(prow + 8);
        __syncthreads();

        {
            const float* ap = a_sm + seg * 16;
            const __half2* ph = (const __half2*)pf;
            u32 hw[8];
#pragma unroll
            for (int i = 0; i < 8; i++) {
                float2 p2 = __half22float2(ph[i]);
                float x0 = fmaxf(p2.x + ap[2*i],     0.f);
                float x1 = fmaxf(p2.y + ap[2*i + 1], 0.f);
                hw[i] = h2u(__floats2half2_rn(x0, x1));
            }
            const u32 c0 = (u32)(seg * 2);
            const u32 off0 = hrow_off + ((c0 ^ qr) << 4);
            const u32 off1 = hrow_off + (((c0 + 1u) ^ qr) << 4);
            asm volatile("st.shared.v4.b32 [%0], {%1,%2,%3,%4};"
                :: "r"(sb + S2_H(0) + off0), "r"(hw[0]), "r"(hw[1]), "r"(hw[2]), "r"(hw[3]) : "memory");
            asm volatile("st.shared.v4.b32 [%0], {%1,%2,%3,%4};"
                :: "r"(sb + S2_H(0) + off1), "r"(hw[4]), "r"(hw[5]), "r"(hw[6]), "r"(hw[7]) : "memory");
        }
        cpasync_wait0();

        int buf = 0;
        for (int ch = 0; ch < 8; ch++) {
            __syncthreads();
            const int nb = buf ^ 1;
            if (ch < 7) {
                const char* srcB = (const char*)(Bimg + (size_t)(ch + 1) * (BROWS * 64));
                u32 dstB = sb + S2_B(nb);
                for (int e = tid; e < 1088; e += 256)
                    cpasync16(dstB + e * 16, srcB + e * 16);
                cpasync_commit();
                const __half* ps = prow + (ch + 1) * 64;
                pf[0] = *(const uint4*)(ps);
                pf[1] = *(const uint4*)(ps + 8);
            }

            const u32 hH = sb + S2_H(buf);
            const u32 bB = sb + S2_B(buf);
#pragma unroll
            for (int ks = 0; ks < 4; ks++) {
                u32 ah[4];
                {
                    int ra = wm * 16 + (l & 15);
                    u32 qa = ((u32)ra >> 3) & 3;
                    u32 chk = (((u32)(l >> 4) + 2u * ks) ^ qa) << 4;
                    ldm_x4(ah, hH + (u32)(ra * 144) + chk);
                }
#pragma unroll
                for (int p = 0; p < 4; p++) {
                    int rb = wn * 72 + p * 16 + (l & 7) + ((l >> 4) & 1) * 8;
                    u32 chunkf = 2u * ks + ((u32)(l >> 3) & 1u);
                    u32 bb[4];
                    ldm_x4(bb, bB + (u32)(rb << 7) + ((chunkf ^ ((u32)rb & 7u)) << 4));
#pragma unroll
                    for (int t = 0; t < 2; t++)
                        mma_f16(acc[p * 2 + t], ah, &bb[2 * t]);
                }
                {
                    int rb2 = 64 + (l & 7);
                    u32 chunkf = 2u * ks + ((u32)(l >> 3) & 1u);
                    u32 s2[2];
                    ldm_x2(s2, bB + (u32)(rb2 << 7) + ((chunkf ^ ((u32)rb2 & 7u)) << 4));
                    mma_f16(acc[8], ah, s2);
                }
            }

            if (ch < 7) {
                const float* ap = a_sm + (ch + 1) * 64 + seg * 16;
                const __half2* ph = (const __half2*)pf;
                u32 hw[8];
#pragma unroll
                for (int i = 0; i < 8; i++) {
                    float2 p2 = __half22float2(ph[i]);
                    float x0 = fmaxf(p2.x + ap[2*i],     0.f);
                    float x1 = fmaxf(p2.y + ap[2*i + 1], 0.f);
                    hw[i] = h2u(__floats2half2_rn(x0, x1));
                }
                const u32 c0 = (u32)(seg * 2);
                const u32 off0 = hrow_off + ((c0 ^ qr) << 4);
                const u32 off1 = hrow_off + (((c0 + 1u) ^ qr) << 4);
                asm volatile("st.shared.v4.b32 [%0], {%1,%2,%3,%4};"
                    :: "r"(sb + S2_H(nb) + off0), "r"(hw[0]), "r"(hw[1]), "r"(hw[2]), "r"(hw[3]) : "memory");
                asm volatile("st.shared.v4.b32 [%0], {%1,%2,%3,%4};"
                    :: "r"(sb + S2_H(nb) + off1), "r"(hw[4]), "r"(hw[5]), "r"(hw[6]), "r"(hw[7]) : "memory");
                cpasync_wait0();
            }
            buf = nb;
        }

        const int g = l >> 2, tg = l & 3;
        const int i0 = ibase + wm * 16 + g;
        const int i1 = i0 + 8;
        const bool ok0 = i0 < cntb, ok1 = i1 < cntb;
        const int v0 = ok0 ? idx[b * VV + i0] : 0;
        const int v1 = ok1 ? idx[b * VV + i1] : 0;
#pragma unroll
        for (int nt = 0; nt < 9; nt++) {
            const int cbase = wn * 72 + nt * 8 + tg * 2;
#pragma unroll
            for (int q = 0; q < 2; q++) {
                const int col = cbase + q;
                if (col >= CC) continue;
                const float bias = __ldg(&b2[col]);
                if (ok0) sem[((size_t)b * CC + col) * VV + v0] = acc[nt][q] + bias;
                if (ok1) sem[((size_t)b * CC + col) * VV + v1] = acc[nt][2 + q] + bias;
            }
        }
    }
}

// ---------------------------------------------------------------------------
extern "C" void kernel_launch(void* const* d_in, const int* in_sizes, int n_in,
                              void* d_out, int out_size)
{
    const float* features  = (const float*)d_in[0];
    const float* W_contact = (const float*)d_in[3];
    const float* b_contact = (const float*)d_in[4];
    const float* Wv        = (const float*)d_in[7];
    const float* Wo        = (const float*)d_in[8];
    const float* W_cls     = (const float*)d_in[9];
    const float* b_cls     = (const float*)d_in[10];
    const float* pos_emb   = (const float*)d_in[11];
    const float* W_ft1     = (const float*)d_in[12];
    const float* b_ft1     = (const float*)d_in[13];
    const float* W_ft2     = (const float*)d_in[14];
    const float* b_ft2     = (const float*)d_in[15];

    float* out  = (float*)d_out;
    float* cont = out;                  // [16, 6890]
    float* sem  = out + BB * VV;        // [16, 133, 6890]

    float *part, *tmp, *att, *a;
    __half *Ph, *Bimg, *B1h;
    int *idx, *cnt;
    cudaGetSymbolAddress((void**)&part,  g_part);
    cudaGetSymbolAddress((void**)&tmp,   g_tmp);
    cudaGetSymbolAddress((void**)&att,   g_att);
    cudaGetSymbolAddress((void**)&a,     g_a);
    cudaGetSymbolAddress((void**)&Ph,    g_Ph);
    cudaGetSymbolAddress((void**)&idx,   g_idx);
    cudaGetSymbolAddress((void**)&cnt,   g_cnt);
    cudaGetSymbolAddress((void**)&Bimg,  g_Bimg);
    cudaGetSymbolAddress((void**)&B1h,   g_B1h);

    cudaFuncSetAttribute(k_sem_mma, cudaFuncAttributeMaxDynamicSharedMemorySize, S2_TOT);
    cudaFuncSetAttribute(k_front,   cudaFuncAttributeMaxDynamicSharedMemorySize, SMF_TOT);

    // front-end: prep + chain + P (single-staged tiles) overlapped/tail
    k_front<<<NPERS, 512, SMF_TOT>>>(features, W_contact, b_contact, Wv, Wo,
                                     W_cls, b_cls, W_ft1, b_ft1, W_ft2,
                                     pos_emb, part, tmp, att, a, cont,
                                     idx, cnt, Bimg, B1h, Ph);

    // main GEMM: 64-row tiles, 2 CTAs/SM
    k_sem_mma<<<NSEM, 256, S2_TOT>>>(a, Ph, Bimg, b_ft2, idx, cnt, sem);
}